// round 3
// baseline (speedup 1.0000x reference)
#include <cuda_runtime.h>
#include <math_constants.h>
#include <math.h>

// Problem constants
#define B_    32
#define R_    200
#define N_    200
#define D_    128
#define H_    8
#define QK_   16
#define KNN_  10
#define CLIP_ 10.0f
#define ROWS_    (B_ * R_)   // 6400 decoder rows
#define ENCROWS_ (B_ * N_)   // 6400 encoder rows

// ---------------------------------------------------------------------------
// Scratch (device globals — no allocation allowed)
// ---------------------------------------------------------------------------
__device__ float g_bflat[(size_t)ROWS_ * KNN_ * D_];  // [6400,1280]
__device__ float g_h1[(size_t)ROWS_ * 5 * D_];        // [6400,640]
__device__ float g_unv[(size_t)ROWS_ * D_];
__device__ float g_cur[(size_t)ROWS_ * D_];
__device__ float g_q[(size_t)ROWS_ * D_];             // [b*R+r][h*16+qk]
__device__ float g_k[(size_t)ENCROWS_ * D_];          // [b*N+n][h*16+qk]
__device__ float g_v[(size_t)ENCROWS_ * D_];
__device__ float g_att[(size_t)ROWS_ * D_];
__device__ float g_mh[(size_t)ROWS_ * D_];
__device__ int   g_knn[(size_t)ROWS_ * KNN_];

// ---------------------------------------------------------------------------
// 1) kNN: per (b,r), 10 smallest masked distances (stable, ascending)
// ---------------------------------------------------------------------------
__global__ void knn_kernel(const float* __restrict__ distance,
                           const float* __restrict__ ninf,
                           const int* __restrict__ current)
{
    int row = blockIdx.x * blockDim.x + threadIdx.x;
    if (row >= ROWS_) return;
    int b = row / R_;
    int cur = current[row];
    const float* dist = distance + ((size_t)b * N_ + cur) * N_;
    const float* mp = ninf + (size_t)row * N_;

    float vals[KNN_];
    int ids[KNN_];
#pragma unroll
    for (int j = 0; j < KNN_; j++) { vals[j] = CUDART_INF_F; ids[j] = N_; }

    for (int n = 0; n < N_; n++) {
        float m = mp[n];
        float dm = isinf(m) ? CUDART_INF_F : dist[n];
        if (dm < vals[KNN_ - 1]) {
            vals[KNN_ - 1] = dm; ids[KNN_ - 1] = n;
#pragma unroll
            for (int j = KNN_ - 1; j > 0; j--) {
                if (vals[j] < vals[j - 1]) {   // strict < keeps earlier index first on ties
                    float tv = vals[j]; vals[j] = vals[j - 1]; vals[j - 1] = tv;
                    int ti = ids[j]; ids[j] = ids[j - 1]; ids[j - 1] = ti;
                }
            }
        }
    }
#pragma unroll
    for (int j = 0; j < KNN_; j++) g_knn[(size_t)row * KNN_ + j] = ids[j];
}

// ---------------------------------------------------------------------------
// 2) gather + pad-avg -> b_flat ; also gather current embedding
// ---------------------------------------------------------------------------
__global__ void gather_kernel(const float* __restrict__ enc,
                              const int* __restrict__ current)
{
    int row = blockIdx.x;
    int b = row / R_;
    int d = threadIdx.x;  // 128
    __shared__ int sid[KNN_];
    __shared__ int scnt;
    if (d < KNN_) sid[d] = g_knn[(size_t)row * KNN_ + d];
    __syncthreads();
    if (d == 0) {
        int c = 0;
#pragma unroll
        for (int j = 0; j < KNN_; j++) c += (sid[j] < N_);
        scnt = c;
    }
    __syncthreads();

    float v[KNN_];
    float sum = 0.f;
#pragma unroll
    for (int j = 0; j < KNN_; j++) {
        int id = sid[j];
        float x = (id < N_) ? enc[((size_t)b * N_ + id) * D_ + d] : 0.f;
        v[j] = x; sum += x;
    }
    float mean = sum / fmaxf((float)scnt, 1e-9f);
#pragma unroll
    for (int j = 0; j < KNN_; j++)
        g_bflat[(size_t)row * (KNN_ * D_) + j * D_ + d] = (sid[j] < N_) ? v[j] : mean;

    int cur = current[row];
    g_cur[(size_t)row * D_ + d] = enc[((size_t)b * N_ + cur) * D_ + d];
}

// ---------------------------------------------------------------------------
// Generic tiled fp32 GEMM: C = [accum? C:0] + A[M,Kd] @ W[Kd,Nd] + bias, opt ReLU
// ---------------------------------------------------------------------------
template <int BM, int BN, int BK, int TM, int TN>
__global__ void gemm_kernel(const float* __restrict__ A, const float* __restrict__ W,
                            const float* __restrict__ bias, float* __restrict__ C,
                            int M, int Nd, int Kd, int relu, int accum)
{
    constexpr int THREADS = (BM / TM) * (BN / TN);
    __shared__ float As[BK][BM];
    __shared__ float Bs[BK][BN];
    const int tid = threadIdx.x;
    const int tcols = BN / TN;
    const int tx = tid % tcols;
    const int ty = tid / tcols;
    const int row0 = blockIdx.y * BM;
    const int col0 = blockIdx.x * BN;

    float acc[TM][TN];
#pragma unroll
    for (int i = 0; i < TM; i++)
#pragma unroll
        for (int j = 0; j < TN; j++) acc[i][j] = 0.f;

    for (int k0 = 0; k0 < Kd; k0 += BK) {
#pragma unroll
        for (int i = tid; i < BM * BK; i += THREADS) {
            int m = i / BK, kk = i % BK;
            int gm = row0 + m;
            As[kk][m] = (gm < M) ? A[(size_t)gm * Kd + k0 + kk] : 0.f;
        }
#pragma unroll
        for (int i = tid; i < BK * BN; i += THREADS) {
            int kk = i / BN, n = i % BN;
            int gn = col0 + n;
            Bs[kk][n] = (gn < Nd) ? W[(size_t)(k0 + kk) * Nd + gn] : 0.f;
        }
        __syncthreads();
#pragma unroll
        for (int kk = 0; kk < BK; kk++) {
            float a[TM], bb[TN];
#pragma unroll
            for (int i = 0; i < TM; i++) a[i] = As[kk][ty * TM + i];
#pragma unroll
            for (int j = 0; j < TN; j++) bb[j] = Bs[kk][tx * TN + j];
#pragma unroll
            for (int i = 0; i < TM; i++)
#pragma unroll
                for (int j = 0; j < TN; j++) acc[i][j] += a[i] * bb[j];
        }
        __syncthreads();
    }

#pragma unroll
    for (int i = 0; i < TM; i++) {
        int gm = row0 + ty * TM + i;
        if (gm >= M) continue;
#pragma unroll
        for (int j = 0; j < TN; j++) {
            int gn = col0 + tx * TN + j;
            if (gn >= Nd) continue;
            float r = acc[i][j];
            if (bias) r += bias[gn];
            if (accum) r += C[(size_t)gm * Nd + gn];
            if (relu) r = fmaxf(r, 0.f);
            C[(size_t)gm * Nd + gn] = r;
        }
    }
}

// ---------------------------------------------------------------------------
// Attention: block per (b,r); warp per head. QK=16, N=200.
// ---------------------------------------------------------------------------
__global__ void attn_kernel(const float* __restrict__ ninf)
{
    int row = blockIdx.x;
    int b = row / R_;
    int h = threadIdx.x >> 5;
    int lane = threadIdx.x & 31;
    __shared__ float sw[H_][N_];

    // broadcast q[h][0..15] into registers
    const float* qp = g_q + (size_t)row * D_ + h * QK_;
    float ql = (lane < QK_) ? qp[lane] : 0.f;
    float qv[QK_];
#pragma unroll
    for (int d = 0; d < QK_; d++) qv[d] = __shfl_sync(0xffffffffu, ql, d);

    const float* kb = g_k + (size_t)b * N_ * D_ + h * QK_;
    const float* maskp = ninf + (size_t)row * N_;

    // pass 1: scores + max
    float mx = -CUDART_INF_F;
    for (int n0 = 0; n0 < N_; n0 += 32) {
        int n = n0 + lane;
        float s = -CUDART_INF_F;
        if (n < N_) {
            const float* kp = kb + (size_t)n * D_;
            float a = 0.f;
#pragma unroll
            for (int d = 0; d < QK_; d++) a += qv[d] * kp[d];
            s = a * 0.25f + maskp[n];   // 1/sqrt(16)
            sw[h][n] = s;
        }
        mx = fmaxf(mx, s);
    }
#pragma unroll
    for (int off = 16; off > 0; off >>= 1)
        mx = fmaxf(mx, __shfl_xor_sync(0xffffffffu, mx, off));

    // pass 2: exp + sum (store weights)
    float sum = 0.f;
    for (int n0 = 0; n0 < N_; n0 += 32) {
        int n = n0 + lane;
        if (n < N_) {
            float w = __expf(sw[h][n] - mx);
            sw[h][n] = w;
            sum += w;
        }
    }
#pragma unroll
    for (int off = 16; off > 0; off >>= 1)
        sum += __shfl_xor_sync(0xffffffffu, sum, off);
    float inv = 1.f / sum;
    __syncwarp();

    // pass 3: lanes 0..15 each own one output dim
    if (lane < QK_) {
        const float* vb = g_v + (size_t)b * N_ * D_ + h * QK_ + lane;
        float acc = 0.f;
#pragma unroll 4
        for (int n = 0; n < N_; n++) acc += sw[h][n] * vb[(size_t)n * D_];
        g_att[(size_t)row * D_ + h * QK_ + lane] = acc * inv;
    }
}

// ---------------------------------------------------------------------------
// Final: sh = mh · enc^T / sqrt(128); logits = 10*tanh(sh)+mask; softmax
// ---------------------------------------------------------------------------
__global__ void final_kernel(const float* __restrict__ enc,
                             const float* __restrict__ ninf,
                             float* __restrict__ out)
{
    int row = blockIdx.x;
    int b = row / R_;
    int tid = threadIdx.x;  // 256
    __shared__ float mhs[D_];
    __shared__ float red[256];

    if (tid < D_) mhs[tid] = g_mh[(size_t)row * D_ + tid];
    __syncthreads();

    float lg = -CUDART_INF_F;
    if (tid < N_) {
        const float* ep = enc + ((size_t)b * N_ + tid) * D_;
        float acc = 0.f;
#pragma unroll 4
        for (int d = 0; d < D_; d++) acc += mhs[d] * ep[d];
        float sh = acc * 0.08838834764831845f;  // 1/sqrt(128)
        lg = CLIP_ * tanhf(sh) + ninf[(size_t)row * N_ + tid];
    }

    // block max
    red[tid] = lg; __syncthreads();
    for (int s = 128; s > 0; s >>= 1) {
        if (tid < s) red[tid] = fmaxf(red[tid], red[tid + s]);
        __syncthreads();
    }
    float mx = red[0];
    __syncthreads();

    float e = (tid < N_) ? __expf(lg - mx) : 0.f;
    red[tid] = e; __syncthreads();
    for (int s = 128; s > 0; s >>= 1) {
        if (tid < s) red[tid] += red[tid + s];
        __syncthreads();
    }
    float inv = 1.f / red[0];
    if (tid < N_) out[(size_t)row * N_ + tid] = e * inv;
}

// ---------------------------------------------------------------------------
// Host: launch pipeline (graph-capturable, allocation-free)
// ---------------------------------------------------------------------------
extern "C" void kernel_launch(void* const* d_in, const int* in_sizes, int n_in,
                              void* d_out, int out_size)
{
    const float* enc  = (const float*)d_in[0];
    const float* dist = (const float*)d_in[1];
    const float* mask = (const float*)d_in[2];
    const int*   cur  = (const int*)d_in[3];
    const float* Wq   = (const float*)d_in[4];
    const float* Wk   = (const float*)d_in[5];
    const float* Wv   = (const float*)d_in[6];
    const float* Wmhc = (const float*)d_in[7];
    const float* bmhc = (const float*)d_in[8];
    const float* W1   = (const float*)d_in[9];
    const float* b1   = (const float*)d_in[10];
    const float* W2   = (const float*)d_in[11];
    const float* b2   = (const float*)d_in[12];
    float* out = (float*)d_out;

    float *p_bflat, *p_h, *p_unv, *p_cur, *p_q, *p_k, *p_v, *p_att, *p_mh;
    cudaGetSymbolAddress((void**)&p_bflat, g_bflat);
    cudaGetSymbolAddress((void**)&p_h,     g_h1);
    cudaGetSymbolAddress((void**)&p_unv,   g_unv);
    cudaGetSymbolAddress((void**)&p_cur,   g_cur);
    cudaGetSymbolAddress((void**)&p_q,     g_q);
    cudaGetSymbolAddress((void**)&p_k,     g_k);
    cudaGetSymbolAddress((void**)&p_v,     g_v);
    cudaGetSymbolAddress((void**)&p_att,   g_att);
    cudaGetSymbolAddress((void**)&p_mh,    g_mh);

    knn_kernel<<<(ROWS_ + 255) / 256, 256>>>(dist, mask, cur);
    gather_kernel<<<ROWS_, 128>>>(enc, cur);

    // MLP layer 1: [6400,1280] @ [1280,640] + b1, ReLU
    {
        dim3 grid((5 * D_ + 127) / 128, (ROWS_ + 127) / 128);
        gemm_kernel<128, 128, 8, 8, 8><<<grid, 256>>>(
            p_bflat, W1, b1, p_h, ROWS_, 5 * D_, KNN_ * D_, 1, 0);
    }
    {
        dim3 grid((D_ + 63) / 64, (ROWS_ + 63) / 64);
        // MLP layer 2: [6400,640] @ [640,128] + b2
        gemm_kernel<64, 64, 16, 4, 4><<<grid, 256>>>(
            p_h, W2, b2, p_unv, ROWS_, D_, 5 * D_, 0, 0);
        // q = cur_emb @ Wq[:128] + unv @ Wq[128:]
        gemm_kernel<64, 64, 16, 4, 4><<<grid, 256>>>(
            p_cur, Wq, nullptr, p_q, ROWS_, D_, D_, 0, 0);
        gemm_kernel<64, 64, 16, 4, 4><<<grid, 256>>>(
            p_unv, Wq + D_ * D_, nullptr, p_q, ROWS_, D_, D_, 0, 1);
        // k, v projections over encoder rows
        gemm_kernel<64, 64, 16, 4, 4><<<grid, 256>>>(
            enc, Wk, nullptr, p_k, ENCROWS_, D_, D_, 0, 0);
        gemm_kernel<64, 64, 16, 4, 4><<<grid, 256>>>(
            enc, Wv, nullptr, p_v, ENCROWS_, D_, D_, 0, 0);
    }

    attn_kernel<<<ROWS_, 256>>>(mask);

    {
        dim3 grid((D_ + 63) / 64, (ROWS_ + 63) / 64);
        gemm_kernel<64, 64, 16, 4, 4><<<grid, 256>>>(
            p_att, Wmhc, bmhc, p_mh, ROWS_, D_, D_, 0, 0);
    }

    final_kernel<<<ROWS_, 256>>>(enc, mask, out);
}

// round 4
// speedup vs baseline: 3.2088x; 3.2088x over previous
#include <cuda_runtime.h>
#include <math_constants.h>
#include <math.h>

// Problem constants
#define B_    32
#define R_    200
#define N_    200
#define D_    128
#define H_    8
#define QK_   16
#define KNN_  10
#define CLIP_ 10.0f
#define ROWS_    (B_ * R_)   // 6400 decoder rows

// ---------------------------------------------------------------------------
// Scratch (device globals — no allocation allowed)
// ---------------------------------------------------------------------------
__device__ float g_bflat[(size_t)ROWS_ * KNN_ * D_];  // [6400,1280]
__device__ float g_h1[(size_t)ROWS_ * 5 * D_];        // [6400,640]
__device__ float g_qin[(size_t)ROWS_ * 2 * D_];       // [6400,256] = [cur | unv]
__device__ float g_q[(size_t)ROWS_ * D_];             // [row][h*16+qk]
__device__ float g_kv[(size_t)ROWS_ * 2 * D_];        // [b*N+n][0:128 k | 128:256 v]
__device__ float g_att[(size_t)ROWS_ * D_];
__device__ float g_mh[(size_t)ROWS_ * D_];
__device__ float g_Wkv[(size_t)D_ * 2 * D_];          // [128][256] = [Wk | Wv]
__device__ int   g_knn[(size_t)ROWS_ * KNN_];

// ---------------------------------------------------------------------------
// 1) kNN: per (b,r), 10 smallest masked distances (stable, ascending)
// ---------------------------------------------------------------------------
__global__ void knn_kernel(const float* __restrict__ distance,
                           const float* __restrict__ ninf,
                           const int* __restrict__ current)
{
    int row = blockIdx.x * blockDim.x + threadIdx.x;
    if (row >= ROWS_) return;
    int b = row / R_;
    int cur = current[row];
    const float* dist = distance + ((size_t)b * N_ + cur) * N_;
    const float* mp = ninf + (size_t)row * N_;

    float vals[KNN_];
    int ids[KNN_];
#pragma unroll
    for (int j = 0; j < KNN_; j++) { vals[j] = CUDART_INF_F; ids[j] = N_; }

#pragma unroll 4
    for (int n = 0; n < N_; n++) {
        float m = mp[n];
        float dm = isinf(m) ? CUDART_INF_F : dist[n];
        if (dm < vals[KNN_ - 1]) {
            vals[KNN_ - 1] = dm; ids[KNN_ - 1] = n;
#pragma unroll
            for (int j = KNN_ - 1; j > 0; j--) {
                if (vals[j] < vals[j - 1]) {   // strict < keeps earlier index first on ties
                    float tv = vals[j]; vals[j] = vals[j - 1]; vals[j - 1] = tv;
                    int ti = ids[j]; ids[j] = ids[j - 1]; ids[j - 1] = ti;
                }
            }
        }
    }
#pragma unroll
    for (int j = 0; j < KNN_; j++) g_knn[(size_t)row * KNN_ + j] = ids[j];
}

// ---------------------------------------------------------------------------
// 2) gather + pad-avg -> b_flat ; current embedding -> qin[:,0:128]
// ---------------------------------------------------------------------------
__global__ void gather_kernel(const float* __restrict__ enc,
                              const int* __restrict__ current)
{
    int row = blockIdx.x;
    int b = row / R_;
    int d = threadIdx.x;  // 128
    __shared__ int sid[KNN_];
    __shared__ int scnt;
    if (d < KNN_) sid[d] = g_knn[(size_t)row * KNN_ + d];
    __syncthreads();
    if (d == 0) {
        int c = 0;
#pragma unroll
        for (int j = 0; j < KNN_; j++) c += (sid[j] < N_);
        scnt = c;
    }
    __syncthreads();

    float v[KNN_];
    float sum = 0.f;
#pragma unroll
    for (int j = 0; j < KNN_; j++) {
        int id = sid[j];
        float x = (id < N_) ? enc[((size_t)b * N_ + id) * D_ + d] : 0.f;
        v[j] = x; sum += x;
    }
    float mean = sum / fmaxf((float)scnt, 1e-9f);
#pragma unroll
    for (int j = 0; j < KNN_; j++)
        g_bflat[(size_t)row * (KNN_ * D_) + j * D_ + d] = (sid[j] < N_) ? v[j] : mean;

    int cur = current[row];
    g_qin[(size_t)row * (2 * D_) + d] = enc[((size_t)b * N_ + cur) * D_ + d];
}

// ---------------------------------------------------------------------------
// pack [Wk | Wv] -> g_Wkv [128][256]
// ---------------------------------------------------------------------------
__global__ void pack_kv_kernel(const float* __restrict__ Wk,
                               const float* __restrict__ Wv)
{
    int i = blockIdx.x * blockDim.x + threadIdx.x;   // 0 .. 128*256-1
    if (i >= D_ * 2 * D_) return;
    int k = i / (2 * D_);
    int n = i % (2 * D_);
    g_Wkv[i] = (n < D_) ? Wk[(size_t)k * D_ + n] : Wv[(size_t)k * D_ + (n - D_)];
}

// ---------------------------------------------------------------------------
// Double-buffered fp32 GEMM. BM=BN=64, BK=16, TM=TN=4, 256 threads.
// M, Nd, Kd all divisible by tile dims (true for every call site).
// C = A[M,Kd](lda) @ W[Kd,Nd](ldb=Nd) (+bias) (ReLU?) -> C(ldc)
// ---------------------------------------------------------------------------
__global__ void __launch_bounds__(256, 4)
gemm2_kernel(const float* __restrict__ A, const float* __restrict__ W,
             const float* __restrict__ bias, float* __restrict__ C,
             int Nd, int Kd, int lda, int ldc, int relu)
{
    constexpr int BM = 64, BN = 64, BK = 16;
    __shared__ float As[2][BK][BM + 4];
    __shared__ float Bs[2][BK][BN + 4];

    const int tid = threadIdx.x;
    const int tx = tid & 15;          // 0..15 (cols)
    const int ty = tid >> 4;          // 0..15 (rows)
    const int row0 = blockIdx.y * BM;
    const int col0 = blockIdx.x * BN;

    // A ldg mapping: thread -> (row am, k-offset ak), one float4
    const int am = tid >> 2;          // 0..63
    const int ak = (tid & 3) * 4;     // 0,4,8,12
    // B ldg mapping: thread -> (k-row bk, col bn), one float4
    const int bk = tid >> 4;          // 0..15
    const int bn = (tid & 15) * 4;    // 0..60

    const int TILES = Kd / BK;

    float4 ra, rb;
    // prologue: tile 0
    ra = *(const float4*)&A[(size_t)(row0 + am) * lda + ak];
    rb = *(const float4*)&W[(size_t)bk * Nd + col0 + bn];
    As[0][ak + 0][am] = ra.x; As[0][ak + 1][am] = ra.y;
    As[0][ak + 2][am] = ra.z; As[0][ak + 3][am] = ra.w;
    *(float4*)&Bs[0][bk][bn] = rb;
    __syncthreads();

    float acc[4][4];
#pragma unroll
    for (int i = 0; i < 4; i++)
#pragma unroll
        for (int j = 0; j < 4; j++) acc[i][j] = 0.f;

    for (int t = 0; t < TILES; t++) {
        int buf = t & 1;
        if (t + 1 < TILES) {
            ra = *(const float4*)&A[(size_t)(row0 + am) * lda + (t + 1) * BK + ak];
            rb = *(const float4*)&W[(size_t)((t + 1) * BK + bk) * Nd + col0 + bn];
        }
#pragma unroll
        for (int kk = 0; kk < BK; kk++) {
            float4 av = *(const float4*)&As[buf][kk][ty * 4];
            float4 bv = *(const float4*)&Bs[buf][kk][tx * 4];
            float a[4] = {av.x, av.y, av.z, av.w};
            float b[4] = {bv.x, bv.y, bv.z, bv.w};
#pragma unroll
            for (int i = 0; i < 4; i++)
#pragma unroll
                for (int j = 0; j < 4; j++) acc[i][j] += a[i] * b[j];
        }
        if (t + 1 < TILES) {
            int nb = buf ^ 1;
            As[nb][ak + 0][am] = ra.x; As[nb][ak + 1][am] = ra.y;
            As[nb][ak + 2][am] = ra.z; As[nb][ak + 3][am] = ra.w;
            *(float4*)&Bs[nb][bk][bn] = rb;
        }
        __syncthreads();
    }

    float bs[4] = {0.f, 0.f, 0.f, 0.f};
    if (bias) {
#pragma unroll
        for (int j = 0; j < 4; j++) bs[j] = bias[col0 + tx * 4 + j];
    }
#pragma unroll
    for (int i = 0; i < 4; i++) {
        int gm = row0 + ty * 4 + i;
        float4 r;
        float rr[4];
#pragma unroll
        for (int j = 0; j < 4; j++) {
            float x = acc[i][j] + bs[j];
            rr[j] = relu ? fmaxf(x, 0.f) : x;
        }
        r.x = rr[0]; r.y = rr[1]; r.z = rr[2]; r.w = rr[3];
        *(float4*)&C[(size_t)gm * ldc + col0 + tx * 4] = r;
    }
}

// ---------------------------------------------------------------------------
// Attention: block per (b, h, 8-row tile). 128 threads (4 warps, 2 rows each).
// k/v head-slices staged in smem once per block.
// ---------------------------------------------------------------------------
__global__ void __launch_bounds__(128, 4)
attn_kernel(const float* __restrict__ ninf)
{
    __shared__ float q_s[8][QK_];
    __shared__ float k_s[QK_][N_ + 8];   // [d][n], stride 208
    __shared__ float v_s[N_][QK_];       // [n][d]
    __shared__ float w_s[8][N_];

    const int rtile = blockIdx.x;     // 0..24
    const int h = blockIdx.y;         // 0..7
    const int b = blockIdx.z;         // 0..31
    const int row0 = b * R_ + rtile * 8;
    const int tid = threadIdx.x;
    const int w = tid >> 5;
    const int lane = tid & 31;

    // stage q (8 rows x 16)
    if (tid < 8 * QK_) {
        int rl = tid >> 4, d = tid & 15;
        q_s[rl][d] = g_q[(size_t)(row0 + rl) * D_ + h * QK_ + d];
    }
    // stage k, v head slices
    const float* kvb = g_kv + (size_t)b * N_ * (2 * D_) + h * QK_;
    for (int idx = tid; idx < N_ * QK_; idx += 128) {
        int n = idx >> 4, d = idx & 15;
        k_s[d][n] = kvb[(size_t)n * (2 * D_) + d];
        v_s[n][d] = kvb[(size_t)n * (2 * D_) + D_ + d];
    }
    __syncthreads();

#pragma unroll
    for (int rr = 0; rr < 2; rr++) {
        int rl = w * 2 + rr;
        int row = row0 + rl;
        const float* maskp = ninf + (size_t)row * N_;

        // pass 1: scores + max
        float mx = -CUDART_INF_F;
        for (int n0 = 0; n0 < N_; n0 += 32) {
            int n = n0 + lane;
            float s = -CUDART_INF_F;
            if (n < N_) {
                float a = 0.f;
#pragma unroll
                for (int d = 0; d < QK_; d++) a += q_s[rl][d] * k_s[d][n];
                s = a * 0.25f + maskp[n];
                w_s[rl][n] = s;
            }
            mx = fmaxf(mx, s);
        }
#pragma unroll
        for (int off = 16; off > 0; off >>= 1)
            mx = fmaxf(mx, __shfl_xor_sync(0xffffffffu, mx, off));

        // pass 2: exp + sum
        float sum = 0.f;
        for (int n0 = 0; n0 < N_; n0 += 32) {
            int n = n0 + lane;
            if (n < N_) {
                float e = __expf(w_s[rl][n] - mx);
                w_s[rl][n] = e;
                sum += e;
            }
        }
#pragma unroll
        for (int off = 16; off > 0; off >>= 1)
            sum += __shfl_xor_sync(0xffffffffu, sum, off);
        float inv = 1.f / sum;
        __syncwarp();

        // pass 3: weighted sum of v; lanes split n into even/odd halves
        int d = lane & 15;
        int half = lane >> 4;
        float acc = 0.f;
#pragma unroll 2
        for (int n = half; n < N_; n += 2)
            acc += w_s[rl][n] * v_s[n][d];
        acc += __shfl_xor_sync(0xffffffffu, acc, 16);
        if (lane < QK_)
            g_att[(size_t)row * D_ + h * QK_ + d] = acc * inv;
        __syncwarp();
    }
}

// ---------------------------------------------------------------------------
// Final: block per 8-row tile. sh = mh·enc^T/sqrt(128); 10*tanh+mask; softmax.
// ---------------------------------------------------------------------------
__global__ void __launch_bounds__(256, 4)
final_kernel(const float* __restrict__ enc,
             const float* __restrict__ ninf,
             float* __restrict__ out)
{
    __shared__ float mh_s[8][D_];
    __shared__ float enc_s[32][D_ + 4];  // stride 132
    __shared__ float lg_s[8][N_];

    const int row0 = blockIdx.x * 8;     // 800 blocks; 8-tiles never cross batch
    const int b = row0 / R_;
    const int tid = threadIdx.x;

    // stage mh (8x128) — one float4 per thread
    {
        int r = tid >> 5, dw = tid & 31;
        *(float4*)&mh_s[r][dw * 4] =
            *(const float4*)&g_mh[(size_t)(row0 + r) * D_ + dw * 4];
    }
    __syncthreads();

    const int r = tid >> 5;      // 0..7
    const int nl = tid & 31;     // 0..31
    const float* encb = enc + (size_t)b * N_ * D_;

    for (int n0 = 0; n0 < N_; n0 += 32) {
        int nrem = N_ - n0; if (nrem > 32) nrem = 32;
        // stage enc tile (coalesced float4)
        for (int v = tid; v < 32 * 32; v += 256) {
            int n = v >> 5, dw = v & 31;
            if (n < nrem)
                *(float4*)&enc_s[n][dw * 4] =
                    *(const float4*)&encb[(size_t)(n0 + n) * D_ + dw * 4];
        }
        __syncthreads();
        if (nl < nrem) {
            float acc = 0.f;
#pragma unroll
            for (int d = 0; d < D_; d += 4) {
                float4 m4 = *(const float4*)&mh_s[r][d];
                float4 e4 = *(const float4*)&enc_s[nl][d];
                acc += m4.x * e4.x + m4.y * e4.y + m4.z * e4.z + m4.w * e4.w;
            }
            float sh = acc * 0.08838834764831845f;  // 1/sqrt(128)
            lg_s[r][n0 + nl] = CLIP_ * tanhf(sh)
                             + ninf[(size_t)(row0 + r) * N_ + n0 + nl];
        }
        __syncthreads();
    }

    // softmax: warp w owns row w
    const int w = tid >> 5;
    const int lane = tid & 31;
    float mx = -CUDART_INF_F;
    for (int n = lane; n < N_; n += 32) mx = fmaxf(mx, lg_s[w][n]);
#pragma unroll
    for (int off = 16; off > 0; off >>= 1)
        mx = fmaxf(mx, __shfl_xor_sync(0xffffffffu, mx, off));
    float sum = 0.f;
    for (int n = lane; n < N_; n += 32) {
        float e = __expf(lg_s[w][n] - mx);
        lg_s[w][n] = e;
        sum += e;
    }
#pragma unroll
    for (int off = 16; off > 0; off >>= 1)
        sum += __shfl_xor_sync(0xffffffffu, sum, off);
    float inv = 1.f / sum;
    for (int n = lane; n < N_; n += 32)
        out[(size_t)(row0 + w) * N_ + n] = lg_s[w][n] * inv;
}

// ---------------------------------------------------------------------------
// Host: launch pipeline (graph-capturable, allocation-free)
// ---------------------------------------------------------------------------
extern "C" void kernel_launch(void* const* d_in, const int* in_sizes, int n_in,
                              void* d_out, int out_size)
{
    const float* enc  = (const float*)d_in[0];
    const float* dist = (const float*)d_in[1];
    const float* mask = (const float*)d_in[2];
    const int*   cur  = (const int*)d_in[3];
    const float* Wq   = (const float*)d_in[4];
    const float* Wk   = (const float*)d_in[5];
    const float* Wv   = (const float*)d_in[6];
    const float* Wmhc = (const float*)d_in[7];
    const float* bmhc = (const float*)d_in[8];
    const float* W1   = (const float*)d_in[9];
    const float* b1   = (const float*)d_in[10];
    const float* W2   = (const float*)d_in[11];
    const float* b2   = (const float*)d_in[12];
    float* out = (float*)d_out;

    float *p_bflat, *p_h, *p_qin, *p_q, *p_kv, *p_att, *p_mh, *p_Wkv;
    cudaGetSymbolAddress((void**)&p_bflat, g_bflat);
    cudaGetSymbolAddress((void**)&p_h,     g_h1);
    cudaGetSymbolAddress((void**)&p_qin,   g_qin);
    cudaGetSymbolAddress((void**)&p_q,     g_q);
    cudaGetSymbolAddress((void**)&p_kv,    g_kv);
    cudaGetSymbolAddress((void**)&p_att,   g_att);
    cudaGetSymbolAddress((void**)&p_mh,    g_mh);
    cudaGetSymbolAddress((void**)&p_Wkv,   g_Wkv);

    knn_kernel<<<(ROWS_ + 255) / 256, 256>>>(dist, mask, cur);
    gather_kernel<<<ROWS_, 128>>>(enc, cur);
    pack_kv_kernel<<<(D_ * 2 * D_ + 255) / 256, 256>>>(Wk, Wv);

    // kv = enc @ [Wk|Wv] : M=6400, N=256, K=128
    gemm2_kernel<<<dim3(4, 100), 256>>>(enc, p_Wkv, nullptr, p_kv,
                                        2 * D_, D_, D_, 2 * D_, 0);
    // h1 = relu(bflat @ W1 + b1) : M=6400, N=640, K=1280
    gemm2_kernel<<<dim3(10, 100), 256>>>(p_bflat, W1, b1, p_h,
                                         5 * D_, KNN_ * D_, KNN_ * D_, 5 * D_, 1);
    // unv = h1 @ W2 + b2 -> qin[:,128:256] : M=6400, N=128, K=640
    gemm2_kernel<<<dim3(2, 100), 256>>>(p_h, W2, b2, p_qin + D_,
                                        D_, 5 * D_, 5 * D_, 2 * D_, 0);
    // q = qin @ Wq : M=6400, N=128, K=256
    gemm2_kernel<<<dim3(2, 100), 256>>>(p_qin, Wq, nullptr, p_q,
                                        D_, 2 * D_, 2 * D_, D_, 0);

    attn_kernel<<<dim3(25, H_, B_), 128>>>(mask);

    // mh = att @ Wmhc + bmhc : M=6400, N=128, K=128
    gemm2_kernel<<<dim3(2, 100), 256>>>(p_att, Wmhc, bmhc, p_mh,
                                        D_, D_, D_, D_, 0);

    final_kernel<<<ROWS_ / 8, 256>>>(enc, mask, out);
}

// round 5
// speedup vs baseline: 3.8019x; 1.1848x over previous
#include <cuda_runtime.h>
#include <math_constants.h>
#include <math.h>

// Problem constants
#define B_    32
#define R_    200
#define N_    200
#define D_    128
#define H_    8
#define QK_   16
#define KNN_  10
#define CLIP_ 10.0f
#define ROWS_    (B_ * R_)   // 6400 decoder rows

// ---------------------------------------------------------------------------
// Scratch (device globals — no allocation allowed)
// ---------------------------------------------------------------------------
__device__ float g_bflat[(size_t)ROWS_ * KNN_ * D_];  // [6400,1280]
__device__ float g_h1[(size_t)ROWS_ * 5 * D_];        // [6400,640]
__device__ float g_qin[(size_t)ROWS_ * 2 * D_];       // [6400,256] = [cur | unv]
__device__ float g_q[(size_t)ROWS_ * D_];             // [row][h*16+qk]
__device__ float g_kv[(size_t)ROWS_ * 2 * D_];        // [b*N+n][0:128 k | 128:256 v]
__device__ float g_att[(size_t)ROWS_ * D_];
__device__ float g_mh[(size_t)ROWS_ * D_];
__device__ float g_Wkv[(size_t)D_ * 2 * D_];          // [128][256] = [Wk | Wv]
__device__ int   g_knn[(size_t)ROWS_ * KNN_];

// ---------------------------------------------------------------------------
// 1) kNN: warp per row. Coalesced loads, 10 warp-argmin extractions.
//    Tie-break: smaller index wins (matches jax.lax.top_k ordering).
// ---------------------------------------------------------------------------
__global__ void __launch_bounds__(256)
knn_kernel(const float* __restrict__ distance,
           const float* __restrict__ ninf,
           const int* __restrict__ current)
{
    const int w = threadIdx.x >> 5;
    const int lane = threadIdx.x & 31;
    const int row = blockIdx.x * 8 + w;          // 800 blocks * 8 warps
    if (row >= ROWS_) return;
    const int b = row / R_;
    const int cur = current[row];
    const float* dist = distance + ((size_t)b * N_ + cur) * N_;
    const float* mp = ninf + (size_t)row * N_;

    float v[7];   // candidate n = lane + 32*i
#pragma unroll
    for (int i = 0; i < 7; i++) {
        int n = lane + 32 * i;
        if (n < N_) {
            float m = mp[n];
            v[i] = isinf(m) ? CUDART_INF_F : dist[n];
        } else {
            v[i] = CUDART_INF_F;
        }
    }

#pragma unroll
    for (int j = 0; j < KNN_; j++) {
        // per-lane argmin (ascending index order -> earliest wins ties)
        float bv = v[0]; int bi = lane;
#pragma unroll
        for (int i = 1; i < 7; i++) {
            if (v[i] < bv) { bv = v[i]; bi = lane + 32 * i; }
        }
        // warp argmin with smaller-index tie break
#pragma unroll
        for (int off = 16; off > 0; off >>= 1) {
            float ov = __shfl_xor_sync(0xffffffffu, bv, off);
            int   oi = __shfl_xor_sync(0xffffffffu, bi, off);
            if (ov < bv || (ov == bv && oi < bi)) { bv = ov; bi = oi; }
        }
        int sel = isinf(bv) ? N_ : bi;
        if (lane == j) g_knn[(size_t)row * KNN_ + j] = sel;
        // remove selected candidate
        if (!isinf(bv) && (bi & 31) == lane) v[bi >> 5] = CUDART_INF_F;
    }
}

// ---------------------------------------------------------------------------
// 2) gather + pad-avg -> b_flat ; current embedding -> qin[:,0:128]
// ---------------------------------------------------------------------------
__global__ void gather_kernel(const float* __restrict__ enc,
                              const int* __restrict__ current)
{
    int row = blockIdx.x;
    int b = row / R_;
    int d = threadIdx.x;  // 128
    __shared__ int sid[KNN_];
    __shared__ int scnt;
    if (d < KNN_) sid[d] = g_knn[(size_t)row * KNN_ + d];
    __syncthreads();
    if (d == 0) {
        int c = 0;
#pragma unroll
        for (int j = 0; j < KNN_; j++) c += (sid[j] < N_);
        scnt = c;
    }
    __syncthreads();

    float v[KNN_];
    float sum = 0.f;
#pragma unroll
    for (int j = 0; j < KNN_; j++) {
        int id = sid[j];
        float x = (id < N_) ? enc[((size_t)b * N_ + id) * D_ + d] : 0.f;
        v[j] = x; sum += x;
    }
    float mean = sum / fmaxf((float)scnt, 1e-9f);
#pragma unroll
    for (int j = 0; j < KNN_; j++)
        g_bflat[(size_t)row * (KNN_ * D_) + j * D_ + d] = (sid[j] < N_) ? v[j] : mean;

    int cur = current[row];
    g_qin[(size_t)row * (2 * D_) + d] = enc[((size_t)b * N_ + cur) * D_ + d];
}

// ---------------------------------------------------------------------------
// pack [Wk | Wv] -> g_Wkv [128][256]
// ---------------------------------------------------------------------------
__global__ void pack_kv_kernel(const float* __restrict__ Wk,
                               const float* __restrict__ Wv)
{
    int i = blockIdx.x * blockDim.x + threadIdx.x;   // 0 .. 128*256-1
    if (i >= D_ * 2 * D_) return;
    int k = i / (2 * D_);
    int n = i % (2 * D_);
    g_Wkv[i] = (n < D_) ? Wk[(size_t)k * D_ + n] : Wv[(size_t)k * D_ + (n - D_)];
}

// ---------------------------------------------------------------------------
// Double-buffered fp32 GEMM. BM=BN=64, BK=16, TM=TN=4, 256 threads.
// (used for the small GEMMs: kv / W2 / q / mhc)
// ---------------------------------------------------------------------------
__global__ void __launch_bounds__(256, 4)
gemm2_kernel(const float* __restrict__ A, const float* __restrict__ W,
             const float* __restrict__ bias, float* __restrict__ C,
             int Nd, int Kd, int lda, int ldc, int relu)
{
    constexpr int BM = 64, BN = 64, BK = 16;
    __shared__ float As[2][BK][BM + 4];
    __shared__ float Bs[2][BK][BN + 4];

    const int tid = threadIdx.x;
    const int tx = tid & 15;
    const int ty = tid >> 4;
    const int row0 = blockIdx.y * BM;
    const int col0 = blockIdx.x * BN;

    const int am = tid >> 2;          // 0..63
    const int ak = (tid & 3) * 4;     // 0,4,8,12
    const int bk = tid >> 4;          // 0..15
    const int bn = (tid & 15) * 4;    // 0..60

    const int TILES = Kd / BK;

    float4 ra, rb;
    ra = *(const float4*)&A[(size_t)(row0 + am) * lda + ak];
    rb = *(const float4*)&W[(size_t)bk * Nd + col0 + bn];
    As[0][ak + 0][am] = ra.x; As[0][ak + 1][am] = ra.y;
    As[0][ak + 2][am] = ra.z; As[0][ak + 3][am] = ra.w;
    *(float4*)&Bs[0][bk][bn] = rb;
    __syncthreads();

    float acc[4][4];
#pragma unroll
    for (int i = 0; i < 4; i++)
#pragma unroll
        for (int j = 0; j < 4; j++) acc[i][j] = 0.f;

    for (int t = 0; t < TILES; t++) {
        int buf = t & 1;
        if (t + 1 < TILES) {
            ra = *(const float4*)&A[(size_t)(row0 + am) * lda + (t + 1) * BK + ak];
            rb = *(const float4*)&W[(size_t)((t + 1) * BK + bk) * Nd + col0 + bn];
        }
#pragma unroll
        for (int kk = 0; kk < BK; kk++) {
            float4 av = *(const float4*)&As[buf][kk][ty * 4];
            float4 bv = *(const float4*)&Bs[buf][kk][tx * 4];
            float a[4] = {av.x, av.y, av.z, av.w};
            float b[4] = {bv.x, bv.y, bv.z, bv.w};
#pragma unroll
            for (int i = 0; i < 4; i++)
#pragma unroll
                for (int j = 0; j < 4; j++) acc[i][j] += a[i] * b[j];
        }
        if (t + 1 < TILES) {
            int nb = buf ^ 1;
            As[nb][ak + 0][am] = ra.x; As[nb][ak + 1][am] = ra.y;
            As[nb][ak + 2][am] = ra.z; As[nb][ak + 3][am] = ra.w;
            *(float4*)&Bs[nb][bk][bn] = rb;
        }
        __syncthreads();
    }

    float bs[4] = {0.f, 0.f, 0.f, 0.f};
    if (bias) {
#pragma unroll
        for (int j = 0; j < 4; j++) bs[j] = bias[col0 + tx * 4 + j];
    }
#pragma unroll
    for (int i = 0; i < 4; i++) {
        int gm = row0 + ty * 4 + i;
        float4 r;
        float rr[4];
#pragma unroll
        for (int j = 0; j < 4; j++) {
            float x = acc[i][j] + bs[j];
            rr[j] = relu ? fmaxf(x, 0.f) : x;
        }
        r.x = rr[0]; r.y = rr[1]; r.z = rr[2]; r.w = rr[3];
        *(float4*)&C[(size_t)gm * ldc + col0 + tx * 4] = r;
    }
}

// ---------------------------------------------------------------------------
// Big-tile fp32 GEMM for W1: BM=BN=128, BK=16, TM=TN=8, 256 threads,
// double buffered. All dims divisible by tile sizes.
// ---------------------------------------------------------------------------
__global__ void __launch_bounds__(256, 2)
gemm128_kernel(const float* __restrict__ A, const float* __restrict__ W,
               const float* __restrict__ bias, float* __restrict__ C,
               int Nd, int Kd, int lda, int ldc, int relu)
{
    constexpr int BM = 128, BN = 128, BK = 16;
    __shared__ float As[2][BK][BM + 4];
    __shared__ float Bs[2][BK][BN + 4];

    const int tid = threadIdx.x;
    const int tx = tid & 15;          // 0..15
    const int ty = tid >> 4;          // 0..15
    const int row0 = blockIdx.y * BM;
    const int col0 = blockIdx.x * BN;

    // A loader: 4 threads per row, thread covers 16B; two row-halves
    const int a_r = tid >> 2;          // 0..63
    const int a_k = (tid & 3) * 4;     // 0,4,8,12
    // B loader: 16 threads per k-row covering 64 cols; two col-halves
    const int b_k = tid >> 4;          // 0..15
    const int b_n = (tid & 15) * 4;    // 0..60

    const int TILES = Kd / BK;

    float4 pa0, pa1, pb0, pb1;

    // prologue: tile 0 -> buffer 0
    pa0 = *(const float4*)&A[(size_t)(row0 + a_r) * lda + a_k];
    pa1 = *(const float4*)&A[(size_t)(row0 + a_r + 64) * lda + a_k];
    pb0 = *(const float4*)&W[(size_t)b_k * Nd + col0 + b_n];
    pb1 = *(const float4*)&W[(size_t)b_k * Nd + col0 + b_n + 64];
    As[0][a_k + 0][a_r] = pa0.x; As[0][a_k + 1][a_r] = pa0.y;
    As[0][a_k + 2][a_r] = pa0.z; As[0][a_k + 3][a_r] = pa0.w;
    As[0][a_k + 0][a_r + 64] = pa1.x; As[0][a_k + 1][a_r + 64] = pa1.y;
    As[0][a_k + 2][a_r + 64] = pa1.z; As[0][a_k + 3][a_r + 64] = pa1.w;
    *(float4*)&Bs[0][b_k][b_n] = pb0;
    *(float4*)&Bs[0][b_k][b_n + 64] = pb1;
    __syncthreads();

    float acc[8][8];
#pragma unroll
    for (int i = 0; i < 8; i++)
#pragma unroll
        for (int j = 0; j < 8; j++) acc[i][j] = 0.f;

    for (int t = 0; t < TILES; t++) {
        const int buf = t & 1;
        if (t + 1 < TILES) {
            const int k0 = (t + 1) * BK;
            pa0 = *(const float4*)&A[(size_t)(row0 + a_r) * lda + k0 + a_k];
            pa1 = *(const float4*)&A[(size_t)(row0 + a_r + 64) * lda + k0 + a_k];
            pb0 = *(const float4*)&W[(size_t)(k0 + b_k) * Nd + col0 + b_n];
            pb1 = *(const float4*)&W[(size_t)(k0 + b_k) * Nd + col0 + b_n + 64];
        }
#pragma unroll
        for (int kk = 0; kk < BK; kk++) {
            float4 a0 = *(const float4*)&As[buf][kk][ty * 8];
            float4 a1 = *(const float4*)&As[buf][kk][ty * 8 + 4];
            float4 b0 = *(const float4*)&Bs[buf][kk][tx * 8];
            float4 b1 = *(const float4*)&Bs[buf][kk][tx * 8 + 4];
            float a[8] = {a0.x, a0.y, a0.z, a0.w, a1.x, a1.y, a1.z, a1.w};
            float b[8] = {b0.x, b0.y, b0.z, b0.w, b1.x, b1.y, b1.z, b1.w};
#pragma unroll
            for (int i = 0; i < 8; i++)
#pragma unroll
                for (int j = 0; j < 8; j++) acc[i][j] += a[i] * b[j];
        }
        if (t + 1 < TILES) {
            const int nb = buf ^ 1;
            As[nb][a_k + 0][a_r] = pa0.x; As[nb][a_k + 1][a_r] = pa0.y;
            As[nb][a_k + 2][a_r] = pa0.z; As[nb][a_k + 3][a_r] = pa0.w;
            As[nb][a_k + 0][a_r + 64] = pa1.x; As[nb][a_k + 1][a_r + 64] = pa1.y;
            As[nb][a_k + 2][a_r + 64] = pa1.z; As[nb][a_k + 3][a_r + 64] = pa1.w;
            *(float4*)&Bs[nb][b_k][b_n] = pb0;
            *(float4*)&Bs[nb][b_k][b_n + 64] = pb1;
        }
        __syncthreads();
    }

    // epilogue
    float bsv[8];
#pragma unroll
    for (int j = 0; j < 8; j++)
        bsv[j] = bias ? bias[col0 + tx * 8 + j] : 0.f;
#pragma unroll
    for (int i = 0; i < 8; i++) {
        const int gm = row0 + ty * 8 + i;
        float rr[8];
#pragma unroll
        for (int j = 0; j < 8; j++) {
            float x = acc[i][j] + bsv[j];
            rr[j] = relu ? fmaxf(x, 0.f) : x;
        }
        float4 r0 = {rr[0], rr[1], rr[2], rr[3]};
        float4 r1 = {rr[4], rr[5], rr[6], rr[7]};
        *(float4*)&C[(size_t)gm * ldc + col0 + tx * 8] = r0;
        *(float4*)&C[(size_t)gm * ldc + col0 + tx * 8 + 4] = r1;
    }
}

// ---------------------------------------------------------------------------
// Attention: block per (b, h, 8-row tile). 128 threads (4 warps, 2 rows each).
// ---------------------------------------------------------------------------
__global__ void __launch_bounds__(128, 4)
attn_kernel(const float* __restrict__ ninf)
{
    __shared__ float q_s[8][QK_];
    __shared__ float k_s[QK_][N_ + 8];   // [d][n]
    __shared__ float v_s[N_][QK_];       // [n][d]
    __shared__ float w_s[8][N_];

    const int rtile = blockIdx.x;     // 0..24
    const int h = blockIdx.y;         // 0..7
    const int b = blockIdx.z;         // 0..31
    const int row0 = b * R_ + rtile * 8;
    const int tid = threadIdx.x;
    const int w = tid >> 5;
    const int lane = tid & 31;

    if (tid < 8 * QK_) {
        int rl = tid >> 4, d = tid & 15;
        q_s[rl][d] = g_q[(size_t)(row0 + rl) * D_ + h * QK_ + d];
    }
    const float* kvb = g_kv + (size_t)b * N_ * (2 * D_) + h * QK_;
    for (int idx = tid; idx < N_ * QK_; idx += 128) {
        int n = idx >> 4, d = idx & 15;
        k_s[d][n] = kvb[(size_t)n * (2 * D_) + d];
        v_s[n][d] = kvb[(size_t)n * (2 * D_) + D_ + d];
    }
    __syncthreads();

#pragma unroll
    for (int rr = 0; rr < 2; rr++) {
        int rl = w * 2 + rr;
        int row = row0 + rl;
        const float* maskp = ninf + (size_t)row * N_;

        float mx = -CUDART_INF_F;
        for (int n0 = 0; n0 < N_; n0 += 32) {
            int n = n0 + lane;
            float s = -CUDART_INF_F;
            if (n < N_) {
                float a = 0.f;
#pragma unroll
                for (int d = 0; d < QK_; d++) a += q_s[rl][d] * k_s[d][n];
                s = a * 0.25f + maskp[n];
                w_s[rl][n] = s;
            }
            mx = fmaxf(mx, s);
        }
#pragma unroll
        for (int off = 16; off > 0; off >>= 1)
            mx = fmaxf(mx, __shfl_xor_sync(0xffffffffu, mx, off));

        float sum = 0.f;
        for (int n0 = 0; n0 < N_; n0 += 32) {
            int n = n0 + lane;
            if (n < N_) {
                float e = __expf(w_s[rl][n] - mx);
                w_s[rl][n] = e;
                sum += e;
            }
        }
#pragma unroll
        for (int off = 16; off > 0; off >>= 1)
            sum += __shfl_xor_sync(0xffffffffu, sum, off);
        float inv = 1.f / sum;
        __syncwarp();

        int d = lane & 15;
        int half = lane >> 4;
        float acc = 0.f;
#pragma unroll 2
        for (int n = half; n < N_; n += 2)
            acc += w_s[rl][n] * v_s[n][d];
        acc += __shfl_xor_sync(0xffffffffu, acc, 16);
        if (lane < QK_)
            g_att[(size_t)row * D_ + h * QK_ + d] = acc * inv;
        __syncwarp();
    }
}

// ---------------------------------------------------------------------------
// Final: block per 8-row tile. sh = mh·enc^T/sqrt(128); 10*tanh+mask; softmax.
// ---------------------------------------------------------------------------
__global__ void __launch_bounds__(256, 4)
final_kernel(const float* __restrict__ enc,
             const float* __restrict__ ninf,
             float* __restrict__ out)
{
    __shared__ float mh_s[8][D_];
    __shared__ float enc_s[32][D_ + 4];
    __shared__ float lg_s[8][N_];

    const int row0 = blockIdx.x * 8;
    const int b = row0 / R_;
    const int tid = threadIdx.x;

    {
        int r = tid >> 5, dw = tid & 31;
        *(float4*)&mh_s[r][dw * 4] =
            *(const float4*)&g_mh[(size_t)(row0 + r) * D_ + dw * 4];
    }
    __syncthreads();

    const int r = tid >> 5;
    const int nl = tid & 31;
    const float* encb = enc + (size_t)b * N_ * D_;

    for (int n0 = 0; n0 < N_; n0 += 32) {
        int nrem = N_ - n0; if (nrem > 32) nrem = 32;
        for (int v = tid; v < 32 * 32; v += 256) {
            int n = v >> 5, dw = v & 31;
            if (n < nrem)
                *(float4*)&enc_s[n][dw * 4] =
                    *(const float4*)&encb[(size_t)(n0 + n) * D_ + dw * 4];
        }
        __syncthreads();
        if (nl < nrem) {
            float acc = 0.f;
#pragma unroll
            for (int d = 0; d < D_; d += 4) {
                float4 m4 = *(const float4*)&mh_s[r][d];
                float4 e4 = *(const float4*)&enc_s[nl][d];
                acc += m4.x * e4.x + m4.y * e4.y + m4.z * e4.z + m4.w * e4.w;
            }
            float sh = acc * 0.08838834764831845f;
            lg_s[r][n0 + nl] = CLIP_ * tanhf(sh)
                             + ninf[(size_t)(row0 + r) * N_ + n0 + nl];
        }
        __syncthreads();
    }

    const int w = tid >> 5;
    const int lane = tid & 31;
    float mx = -CUDART_INF_F;
    for (int n = lane; n < N_; n += 32) mx = fmaxf(mx, lg_s[w][n]);
#pragma unroll
    for (int off = 16; off > 0; off >>= 1)
        mx = fmaxf(mx, __shfl_xor_sync(0xffffffffu, mx, off));
    float sum = 0.f;
    for (int n = lane; n < N_; n += 32) {
        float e = __expf(lg_s[w][n] - mx);
        lg_s[w][n] = e;
        sum += e;
    }
#pragma unroll
    for (int off = 16; off > 0; off >>= 1)
        sum += __shfl_xor_sync(0xffffffffu, sum, off);
    float inv = 1.f / sum;
    for (int n = lane; n < N_; n += 32)
        out[(size_t)(row0 + w) * N_ + n] = lg_s[w][n] * inv;
}

// ---------------------------------------------------------------------------
// Host: launch pipeline (graph-capturable, allocation-free)
// ---------------------------------------------------------------------------
extern "C" void kernel_launch(void* const* d_in, const int* in_sizes, int n_in,
                              void* d_out, int out_size)
{
    const float* enc  = (const float*)d_in[0];
    const float* dist = (const float*)d_in[1];
    const float* mask = (const float*)d_in[2];
    const int*   cur  = (const int*)d_in[3];
    const float* Wq   = (const float*)d_in[4];
    const float* Wk   = (const float*)d_in[5];
    const float* Wv   = (const float*)d_in[6];
    const float* Wmhc = (const float*)d_in[7];
    const float* bmhc = (const float*)d_in[8];
    const float* W1   = (const float*)d_in[9];
    const float* b1   = (const float*)d_in[10];
    const float* W2   = (const float*)d_in[11];
    const float* b2   = (const float*)d_in[12];
    float* out = (float*)d_out;

    float *p_bflat, *p_h, *p_qin, *p_q, *p_kv, *p_att, *p_mh, *p_Wkv;
    cudaGetSymbolAddress((void**)&p_bflat, g_bflat);
    cudaGetSymbolAddress((void**)&p_h,     g_h1);
    cudaGetSymbolAddress((void**)&p_qin,   g_qin);
    cudaGetSymbolAddress((void**)&p_q,     g_q);
    cudaGetSymbolAddress((void**)&p_kv,    g_kv);
    cudaGetSymbolAddress((void**)&p_att,   g_att);
    cudaGetSymbolAddress((void**)&p_mh,    g_mh);
    cudaGetSymbolAddress((void**)&p_Wkv,   g_Wkv);

    knn_kernel<<<ROWS_ / 8, 256>>>(dist, mask, cur);
    gather_kernel<<<ROWS_, 128>>>(enc, cur);
    pack_kv_kernel<<<(D_ * 2 * D_ + 255) / 256, 256>>>(Wk, Wv);

    // kv = enc @ [Wk|Wv] : M=6400, N=256, K=128
    gemm2_kernel<<<dim3(4, 100), 256>>>(enc, p_Wkv, nullptr, p_kv,
                                        2 * D_, D_, D_, 2 * D_, 0);
    // h1 = relu(bflat @ W1 + b1) : M=6400, N=640, K=1280  (big-tile kernel)
    gemm128_kernel<<<dim3(5, 50), 256>>>(p_bflat, W1, b1, p_h,
                                         5 * D_, KNN_ * D_, KNN_ * D_, 5 * D_, 1);
    // unv = h1 @ W2 + b2 -> qin[:,128:256] : M=6400, N=128, K=640
    gemm2_kernel<<<dim3(2, 100), 256>>>(p_h, W2, b2, p_qin + D_,
                                        D_, 5 * D_, 5 * D_, 2 * D_, 0);
    // q = qin @ Wq : M=6400, N=128, K=256
    gemm2_kernel<<<dim3(2, 100), 256>>>(p_qin, Wq, nullptr, p_q,
                                        D_, 2 * D_, 2 * D_, D_, 0);

    attn_kernel<<<dim3(25, H_, B_), 128>>>(mask);

    // mh = att @ Wmhc + bmhc : M=6400, N=128, K=128
    gemm2_kernel<<<dim3(2, 100), 256>>>(p_att, Wmhc, bmhc, p_mh,
                                        D_, D_, D_, D_, 0);

    final_kernel<<<ROWS_ / 8, 256>>>(enc, mask, out);
}

// round 6
// speedup vs baseline: 4.8043x; 1.2637x over previous
#include <cuda_runtime.h>
#include <cuda_bf16.h>
#include <math_constants.h>
#include <math.h>

// Problem constants
#define B_    32
#define R_    200
#define N_    200
#define D_    128
#define H_    8
#define QK_   16
#define KNN_  10
#define CLIP_ 10.0f
#define ROWS_    (B_ * R_)   // 6400 decoder rows

// ---------------------------------------------------------------------------
// Scratch (device globals — no allocation allowed)
// ---------------------------------------------------------------------------
__device__ __nv_bfloat16 g_bflat_h[(size_t)ROWS_ * KNN_ * D_];  // [6400,1280]
__device__ __nv_bfloat16 g_bflat_l[(size_t)ROWS_ * KNN_ * D_];
__device__ __nv_bfloat16 g_h1_h[(size_t)ROWS_ * 5 * D_];        // [6400,640]
__device__ __nv_bfloat16 g_h1_l[(size_t)ROWS_ * 5 * D_];
__device__ __nv_bfloat16 g_w1t_h[(size_t)5 * D_ * KNN_ * D_];   // [640,1280] (transposed)
__device__ __nv_bfloat16 g_w1t_l[(size_t)5 * D_ * KNN_ * D_];
__device__ __nv_bfloat16 g_w2t_h[(size_t)D_ * 5 * D_];          // [128,640]
__device__ __nv_bfloat16 g_w2t_l[(size_t)D_ * 5 * D_];
__device__ float g_qin[(size_t)ROWS_ * 2 * D_];       // [6400,256] = [cur | unv]
__device__ float g_q[(size_t)ROWS_ * D_];
__device__ float g_kv[(size_t)ROWS_ * 2 * D_];        // [b*N+n][0:128 k | 128:256 v]
__device__ float g_att[(size_t)ROWS_ * D_];
__device__ float g_mh[(size_t)ROWS_ * D_];
__device__ float g_Wkv[(size_t)D_ * 2 * D_];          // [128][256] = [Wk | Wv]
__device__ int   g_knn[(size_t)ROWS_ * KNN_];

// ---------------------------------------------------------------------------
// 1) kNN: warp per row.
// ---------------------------------------------------------------------------
__global__ void __launch_bounds__(256)
knn_kernel(const float* __restrict__ distance,
           const float* __restrict__ ninf,
           const int* __restrict__ current)
{
    const int w = threadIdx.x >> 5;
    const int lane = threadIdx.x & 31;
    const int row = blockIdx.x * 8 + w;
    if (row >= ROWS_) return;
    const int b = row / R_;
    const int cur = current[row];
    const float* dist = distance + ((size_t)b * N_ + cur) * N_;
    const float* mp = ninf + (size_t)row * N_;

    float v[7];
#pragma unroll
    for (int i = 0; i < 7; i++) {
        int n = lane + 32 * i;
        if (n < N_) {
            float m = mp[n];
            v[i] = isinf(m) ? CUDART_INF_F : dist[n];
        } else {
            v[i] = CUDART_INF_F;
        }
    }

#pragma unroll
    for (int j = 0; j < KNN_; j++) {
        float bv = v[0]; int bi = lane;
#pragma unroll
        for (int i = 1; i < 7; i++) {
            if (v[i] < bv) { bv = v[i]; bi = lane + 32 * i; }
        }
#pragma unroll
        for (int off = 16; off > 0; off >>= 1) {
            float ov = __shfl_xor_sync(0xffffffffu, bv, off);
            int   oi = __shfl_xor_sync(0xffffffffu, bi, off);
            if (ov < bv || (ov == bv && oi < bi)) { bv = ov; bi = oi; }
        }
        int sel = isinf(bv) ? N_ : bi;
        if (lane == j) g_knn[(size_t)row * KNN_ + j] = sel;
        if (!isinf(bv) && (bi & 31) == lane) v[bi >> 5] = CUDART_INF_F;
    }
}

// ---------------------------------------------------------------------------
// 2) gather + pad-avg -> bflat (bf16 hi/lo) ; current embedding -> qin[:,0:128]
// ---------------------------------------------------------------------------
__global__ void gather_kernel(const float* __restrict__ enc,
                              const int* __restrict__ current)
{
    int row = blockIdx.x;
    int b = row / R_;
    int d = threadIdx.x;  // 128
    __shared__ int sid[KNN_];
    __shared__ int scnt;
    if (d < KNN_) sid[d] = g_knn[(size_t)row * KNN_ + d];
    __syncthreads();
    if (d == 0) {
        int c = 0;
#pragma unroll
        for (int j = 0; j < KNN_; j++) c += (sid[j] < N_);
        scnt = c;
    }
    __syncthreads();

    float v[KNN_];
    float sum = 0.f;
#pragma unroll
    for (int j = 0; j < KNN_; j++) {
        int id = sid[j];
        float x = (id < N_) ? enc[((size_t)b * N_ + id) * D_ + d] : 0.f;
        v[j] = x; sum += x;
    }
    float mean = sum / fmaxf((float)scnt, 1e-9f);
#pragma unroll
    for (int j = 0; j < KNN_; j++) {
        float x = (sid[j] < N_) ? v[j] : mean;
        __nv_bfloat16 hi = __float2bfloat16_rn(x);
        __nv_bfloat16 lo = __float2bfloat16_rn(x - __bfloat162float(hi));
        size_t o = (size_t)row * (KNN_ * D_) + j * D_ + d;
        g_bflat_h[o] = hi;
        g_bflat_l[o] = lo;
    }

    int cur = current[row];
    g_qin[(size_t)row * (2 * D_) + d] = enc[((size_t)b * N_ + cur) * D_ + d];
}

// ---------------------------------------------------------------------------
// pack [Wk | Wv] -> g_Wkv [128][256]
// ---------------------------------------------------------------------------
__global__ void pack_kv_kernel(const float* __restrict__ Wk,
                               const float* __restrict__ Wv)
{
    int i = blockIdx.x * blockDim.x + threadIdx.x;
    if (i >= D_ * 2 * D_) return;
    int k = i / (2 * D_);
    int n = i % (2 * D_);
    g_Wkv[i] = (n < D_) ? Wk[(size_t)k * D_ + n] : Wv[(size_t)k * D_ + (n - D_)];
}

// ---------------------------------------------------------------------------
// Transpose + bf16-split pack: W[K][N] -> T_hi/T_lo [N][K]
// ---------------------------------------------------------------------------
__global__ void pack_w_kernel(const float* __restrict__ W,
                              __nv_bfloat16* __restrict__ Th,
                              __nv_bfloat16* __restrict__ Tl,
                              int K, int Nd)
{
    int i = blockIdx.x * blockDim.x + threadIdx.x;   // over N*K (output index)
    if (i >= K * Nd) return;
    int n = i / K;
    int k = i % K;
    float x = W[(size_t)k * Nd + n];
    __nv_bfloat16 hi = __float2bfloat16_rn(x);
    Th[i] = hi;
    Tl[i] = __float2bfloat16_rn(x - __bfloat162float(hi));
}

// ---------------------------------------------------------------------------
// Split-bf16 tensor GEMM: C = A @ B^T (+bias) with A=[M,K] (hi/lo bf16,
// k-major), B=[N,K] (hi/lo bf16, k-major). 3 HMMA passes: ah*bh+ah*bl+al*bh.
// Block tile 128x128, BK=16, 8 warps (64x32 each). M,N multiples of 128,
// K multiple of 16.
// SPLIT_OUT=1: write bf16 hi/lo pair (ldc applies). else fp32 to Cf.
// ---------------------------------------------------------------------------
template <int RELU, int SPLIT_OUT>
__global__ void __launch_bounds__(256)
mma_gemm_kernel(const __nv_bfloat16* __restrict__ Ah,
                const __nv_bfloat16* __restrict__ Al,
                const __nv_bfloat16* __restrict__ Bh,
                const __nv_bfloat16* __restrict__ Bl,
                const float* __restrict__ bias,
                float* __restrict__ Cf,
                __nv_bfloat16* __restrict__ Ch,
                __nv_bfloat16* __restrict__ Cl,
                int Kd, int ldc)
{
    // smem: [128 rows][9 uint32]  (8 kpairs + 1 pad), double buffered
    __shared__ unsigned As_h[2][128][9], As_l[2][128][9];
    __shared__ unsigned Bs_h[2][128][9], Bs_l[2][128][9];

    const int tid = threadIdx.x;
    const int lane = tid & 31;
    const int wid = tid >> 5;
    const int wm = (wid & 1) * 64;      // warp row offset
    const int wn = (wid >> 1) * 32;     // warp col offset
    const int row0 = blockIdx.y * 128;
    const int col0 = blockIdx.x * 128;

    // loader mapping: one uint4 (8 bf16) per thread per array
    const int l_r = tid >> 1;           // 0..127
    const int l_c = (tid & 1) * 4;      // uint32 col 0 or 4
    const int l_k = (tid & 1) * 8;      // bf16 k offset 0 or 8

    const size_t a_base = (size_t)(row0 + l_r) * Kd + l_k;
    const size_t b_base = (size_t)(col0 + l_r) * Kd + l_k;

    const int TILES = Kd / 16;

    uint4 pah, pal, pbh, pbl;
    pah = *(const uint4*)&Ah[a_base];
    pal = *(const uint4*)&Al[a_base];
    pbh = *(const uint4*)&Bh[b_base];
    pbl = *(const uint4*)&Bl[b_base];
    {
        const unsigned* u;
        u = (const unsigned*)&pah;
#pragma unroll
        for (int j = 0; j < 4; j++) As_h[0][l_r][l_c + j] = u[j];
        u = (const unsigned*)&pal;
#pragma unroll
        for (int j = 0; j < 4; j++) As_l[0][l_r][l_c + j] = u[j];
        u = (const unsigned*)&pbh;
#pragma unroll
        for (int j = 0; j < 4; j++) Bs_h[0][l_r][l_c + j] = u[j];
        u = (const unsigned*)&pbl;
#pragma unroll
        for (int j = 0; j < 4; j++) Bs_l[0][l_r][l_c + j] = u[j];
    }
    __syncthreads();

    float c[4][4][4];
#pragma unroll
    for (int i = 0; i < 4; i++)
#pragma unroll
        for (int j = 0; j < 4; j++)
#pragma unroll
            for (int r = 0; r < 4; r++) c[i][j][r] = 0.f;

    const int g = lane >> 2;        // group row/col within tile
    const int kp = lane & 3;        // kpair

    for (int t = 0; t < TILES; t++) {
        const int buf = t & 1;
        if (t + 1 < TILES) {
            const size_t ko = (size_t)(t + 1) * 16;
            pah = *(const uint4*)&Ah[a_base + ko];
            pal = *(const uint4*)&Al[a_base + ko];
            pbh = *(const uint4*)&Bh[b_base + ko];
            pbl = *(const uint4*)&Bl[b_base + ko];
        }

        // b fragments: 4 n-tiles x {b0,b1} x {hi,lo}
        unsigned bh0[4], bh1[4], bl0[4], bl1[4];
#pragma unroll
        for (int nt = 0; nt < 4; nt++) {
            const int cb = wn + nt * 8 + g;
            bh0[nt] = Bs_h[buf][cb][kp];
            bh1[nt] = Bs_h[buf][cb][kp + 4];
            bl0[nt] = Bs_l[buf][cb][kp];
            bl1[nt] = Bs_l[buf][cb][kp + 4];
        }
#pragma unroll
        for (int mt = 0; mt < 4; mt++) {
            const int rb = wm + mt * 16 + g;
            unsigned ah0 = As_h[buf][rb][kp];
            unsigned ah1 = As_h[buf][rb + 8][kp];
            unsigned ah2 = As_h[buf][rb][kp + 4];
            unsigned ah3 = As_h[buf][rb + 8][kp + 4];
            unsigned al0 = As_l[buf][rb][kp];
            unsigned al1 = As_l[buf][rb + 8][kp];
            unsigned al2 = As_l[buf][rb][kp + 4];
            unsigned al3 = As_l[buf][rb + 8][kp + 4];
#pragma unroll
            for (int nt = 0; nt < 4; nt++) {
                float* cc = c[mt][nt];
                asm volatile(
                    "mma.sync.aligned.m16n8k16.row.col.f32.bf16.bf16.f32 "
                    "{%0,%1,%2,%3},{%4,%5,%6,%7},{%8,%9},{%0,%1,%2,%3};"
                    : "+f"(cc[0]), "+f"(cc[1]), "+f"(cc[2]), "+f"(cc[3])
                    : "r"(ah0), "r"(ah1), "r"(ah2), "r"(ah3),
                      "r"(bh0[nt]), "r"(bh1[nt]));
                asm volatile(
                    "mma.sync.aligned.m16n8k16.row.col.f32.bf16.bf16.f32 "
                    "{%0,%1,%2,%3},{%4,%5,%6,%7},{%8,%9},{%0,%1,%2,%3};"
                    : "+f"(cc[0]), "+f"(cc[1]), "+f"(cc[2]), "+f"(cc[3])
                    : "r"(ah0), "r"(ah1), "r"(ah2), "r"(ah3),
                      "r"(bl0[nt]), "r"(bl1[nt]));
                asm volatile(
                    "mma.sync.aligned.m16n8k16.row.col.f32.bf16.bf16.f32 "
                    "{%0,%1,%2,%3},{%4,%5,%6,%7},{%8,%9},{%0,%1,%2,%3};"
                    : "+f"(cc[0]), "+f"(cc[1]), "+f"(cc[2]), "+f"(cc[3])
                    : "r"(al0), "r"(al1), "r"(al2), "r"(al3),
                      "r"(bh0[nt]), "r"(bh1[nt]));
            }
        }

        if (t + 1 < TILES) {
            const int nb = buf ^ 1;
            const unsigned* u;
            u = (const unsigned*)&pah;
#pragma unroll
            for (int j = 0; j < 4; j++) As_h[nb][l_r][l_c + j] = u[j];
            u = (const unsigned*)&pal;
#pragma unroll
            for (int j = 0; j < 4; j++) As_l[nb][l_r][l_c + j] = u[j];
            u = (const unsigned*)&pbh;
#pragma unroll
            for (int j = 0; j < 4; j++) Bs_h[nb][l_r][l_c + j] = u[j];
            u = (const unsigned*)&pbl;
#pragma unroll
            for (int j = 0; j < 4; j++) Bs_l[nb][l_r][l_c + j] = u[j];
        }
        __syncthreads();
    }

    // epilogue
#pragma unroll
    for (int mt = 0; mt < 4; mt++) {
#pragma unroll
        for (int nt = 0; nt < 4; nt++) {
            const int row = row0 + wm + mt * 16 + g;
            const int col = col0 + wn + nt * 8 + 2 * kp;
            float b0 = bias ? bias[col] : 0.f;
            float b1 = bias ? bias[col + 1] : 0.f;
            float v00 = c[mt][nt][0] + b0, v01 = c[mt][nt][1] + b1;
            float v10 = c[mt][nt][2] + b0, v11 = c[mt][nt][3] + b1;
            if (RELU) {
                v00 = fmaxf(v00, 0.f); v01 = fmaxf(v01, 0.f);
                v10 = fmaxf(v10, 0.f); v11 = fmaxf(v11, 0.f);
            }
            if (SPLIT_OUT) {
                __nv_bfloat16 h00 = __float2bfloat16_rn(v00);
                __nv_bfloat16 h01 = __float2bfloat16_rn(v01);
                __nv_bfloat16 h10 = __float2bfloat16_rn(v10);
                __nv_bfloat16 h11 = __float2bfloat16_rn(v11);
                __nv_bfloat162 hp0 = {h00, h01};
                __nv_bfloat162 hp1 = {h10, h11};
                __nv_bfloat162 lp0 = {__float2bfloat16_rn(v00 - __bfloat162float(h00)),
                                      __float2bfloat16_rn(v01 - __bfloat162float(h01))};
                __nv_bfloat162 lp1 = {__float2bfloat16_rn(v10 - __bfloat162float(h10)),
                                      __float2bfloat16_rn(v11 - __bfloat162float(h11))};
                *(__nv_bfloat162*)&Ch[(size_t)row * ldc + col] = hp0;
                *(__nv_bfloat162*)&Ch[(size_t)(row + 8) * ldc + col] = hp1;
                *(__nv_bfloat162*)&Cl[(size_t)row * ldc + col] = lp0;
                *(__nv_bfloat162*)&Cl[(size_t)(row + 8) * ldc + col] = lp1;
            } else {
                float2 f0 = {v00, v01};
                float2 f1 = {v10, v11};
                *(float2*)&Cf[(size_t)row * ldc + col] = f0;
                *(float2*)&Cf[(size_t)(row + 8) * ldc + col] = f1;
            }
        }
    }
}

// ---------------------------------------------------------------------------
// Double-buffered fp32 GEMM (small GEMMs: kv / q / mhc)
// ---------------------------------------------------------------------------
__global__ void __launch_bounds__(256, 4)
gemm2_kernel(const float* __restrict__ A, const float* __restrict__ W,
             const float* __restrict__ bias, float* __restrict__ C,
             int Nd, int Kd, int lda, int ldc, int relu)
{
    constexpr int BM = 64, BN = 64, BK = 16;
    __shared__ float As[2][BK][BM + 4];
    __shared__ float Bs[2][BK][BN + 4];

    const int tid = threadIdx.x;
    const int tx = tid & 15;
    const int ty = tid >> 4;
    const int row0 = blockIdx.y * BM;
    const int col0 = blockIdx.x * BN;

    const int am = tid >> 2;
    const int ak = (tid & 3) * 4;
    const int bk = tid >> 4;
    const int bn = (tid & 15) * 4;

    const int TILES = Kd / BK;

    float4 ra, rb;
    ra = *(const float4*)&A[(size_t)(row0 + am) * lda + ak];
    rb = *(const float4*)&W[(size_t)bk * Nd + col0 + bn];
    As[0][ak + 0][am] = ra.x; As[0][ak + 1][am] = ra.y;
    As[0][ak + 2][am] = ra.z; As[0][ak + 3][am] = ra.w;
    *(float4*)&Bs[0][bk][bn] = rb;
    __syncthreads();

    float acc[4][4];
#pragma unroll
    for (int i = 0; i < 4; i++)
#pragma unroll
        for (int j = 0; j < 4; j++) acc[i][j] = 0.f;

    for (int t = 0; t < TILES; t++) {
        int buf = t & 1;
        if (t + 1 < TILES) {
            ra = *(const float4*)&A[(size_t)(row0 + am) * lda + (t + 1) * BK + ak];
            rb = *(const float4*)&W[(size_t)((t + 1) * BK + bk) * Nd + col0 + bn];
        }
#pragma unroll
        for (int kk = 0; kk < BK; kk++) {
            float4 av = *(const float4*)&As[buf][kk][ty * 4];
            float4 bv = *(const float4*)&Bs[buf][kk][tx * 4];
            float a[4] = {av.x, av.y, av.z, av.w};
            float b[4] = {bv.x, bv.y, bv.z, bv.w};
#pragma unroll
            for (int i = 0; i < 4; i++)
#pragma unroll
                for (int j = 0; j < 4; j++) acc[i][j] += a[i] * b[j];
        }
        if (t + 1 < TILES) {
            int nb = buf ^ 1;
            As[nb][ak + 0][am] = ra.x; As[nb][ak + 1][am] = ra.y;
            As[nb][ak + 2][am] = ra.z; As[nb][ak + 3][am] = ra.w;
            *(float4*)&Bs[nb][bk][bn] = rb;
        }
        __syncthreads();
    }

    float bs[4] = {0.f, 0.f, 0.f, 0.f};
    if (bias) {
#pragma unroll
        for (int j = 0; j < 4; j++) bs[j] = bias[col0 + tx * 4 + j];
    }
#pragma unroll
    for (int i = 0; i < 4; i++) {
        int gm = row0 + ty * 4 + i;
        float4 r;
        float rr[4];
#pragma unroll
        for (int j = 0; j < 4; j++) {
            float x = acc[i][j] + bs[j];
            rr[j] = relu ? fmaxf(x, 0.f) : x;
        }
        r.x = rr[0]; r.y = rr[1]; r.z = rr[2]; r.w = rr[3];
        *(float4*)&C[(size_t)gm * ldc + col0 + tx * 4] = r;
    }
}

// ---------------------------------------------------------------------------
// Attention: block per (b, h, 8-row tile). 128 threads.
// ---------------------------------------------------------------------------
__global__ void __launch_bounds__(128, 4)
attn_kernel(const float* __restrict__ ninf)
{
    __shared__ float q_s[8][QK_];
    __shared__ float k_s[QK_][N_ + 8];
    __shared__ float v_s[N_][QK_];
    __shared__ float w_s[8][N_];

    const int rtile = blockIdx.x;
    const int h = blockIdx.y;
    const int b = blockIdx.z;
    const int row0 = b * R_ + rtile * 8;
    const int tid = threadIdx.x;
    const int w = tid >> 5;
    const int lane = tid & 31;

    if (tid < 8 * QK_) {
        int rl = tid >> 4, d = tid & 15;
        q_s[rl][d] = g_q[(size_t)(row0 + rl) * D_ + h * QK_ + d];
    }
    const float* kvb = g_kv + (size_t)b * N_ * (2 * D_) + h * QK_;
    for (int idx = tid; idx < N_ * QK_; idx += 128) {
        int n = idx >> 4, d = idx & 15;
        k_s[d][n] = kvb[(size_t)n * (2 * D_) + d];
        v_s[n][d] = kvb[(size_t)n * (2 * D_) + D_ + d];
    }
    __syncthreads();

#pragma unroll
    for (int rr = 0; rr < 2; rr++) {
        int rl = w * 2 + rr;
        int row = row0 + rl;
        const float* maskp = ninf + (size_t)row * N_;

        float mx = -CUDART_INF_F;
        for (int n0 = 0; n0 < N_; n0 += 32) {
            int n = n0 + lane;
            float s = -CUDART_INF_F;
            if (n < N_) {
                float a = 0.f;
#pragma unroll
                for (int d = 0; d < QK_; d++) a += q_s[rl][d] * k_s[d][n];
                s = a * 0.25f + maskp[n];
                w_s[rl][n] = s;
            }
            mx = fmaxf(mx, s);
        }
#pragma unroll
        for (int off = 16; off > 0; off >>= 1)
            mx = fmaxf(mx, __shfl_xor_sync(0xffffffffu, mx, off));

        float sum = 0.f;
        for (int n0 = 0; n0 < N_; n0 += 32) {
            int n = n0 + lane;
            if (n < N_) {
                float e = __expf(w_s[rl][n] - mx);
                w_s[rl][n] = e;
                sum += e;
            }
        }
#pragma unroll
        for (int off = 16; off > 0; off >>= 1)
            sum += __shfl_xor_sync(0xffffffffu, sum, off);
        float inv = 1.f / sum;
        __syncwarp();

        int d = lane & 15;
        int half = lane >> 4;
        float acc = 0.f;
#pragma unroll 2
        for (int n = half; n < N_; n += 2)
            acc += w_s[rl][n] * v_s[n][d];
        acc += __shfl_xor_sync(0xffffffffu, acc, 16);
        if (lane < QK_)
            g_att[(size_t)row * D_ + h * QK_ + d] = acc * inv;
        __syncwarp();
    }
}

// ---------------------------------------------------------------------------
// Final: block per 8-row tile.
// ---------------------------------------------------------------------------
__global__ void __launch_bounds__(256, 4)
final_kernel(const float* __restrict__ enc,
             const float* __restrict__ ninf,
             float* __restrict__ out)
{
    __shared__ float mh_s[8][D_];
    __shared__ float enc_s[32][D_ + 4];
    __shared__ float lg_s[8][N_];

    const int row0 = blockIdx.x * 8;
    const int b = row0 / R_;
    const int tid = threadIdx.x;

    {
        int r = tid >> 5, dw = tid & 31;
        *(float4*)&mh_s[r][dw * 4] =
            *(const float4*)&g_mh[(size_t)(row0 + r) * D_ + dw * 4];
    }
    __syncthreads();

    const int r = tid >> 5;
    const int nl = tid & 31;
    const float* encb = enc + (size_t)b * N_ * D_;

    for (int n0 = 0; n0 < N_; n0 += 32) {
        int nrem = N_ - n0; if (nrem > 32) nrem = 32;
        for (int v = tid; v < 32 * 32; v += 256) {
            int n = v >> 5, dw = v & 31;
            if (n < nrem)
                *(float4*)&enc_s[n][dw * 4] =
                    *(const float4*)&encb[(size_t)(n0 + n) * D_ + dw * 4];
        }
        __syncthreads();
        if (nl < nrem) {
            float acc = 0.f;
#pragma unroll
            for (int d = 0; d < D_; d += 4) {
                float4 m4 = *(const float4*)&mh_s[r][d];
                float4 e4 = *(const float4*)&enc_s[nl][d];
                acc += m4.x * e4.x + m4.y * e4.y + m4.z * e4.z + m4.w * e4.w;
            }
            float sh = acc * 0.08838834764831845f;
            lg_s[r][n0 + nl] = CLIP_ * tanhf(sh)
                             + ninf[(size_t)(row0 + r) * N_ + n0 + nl];
        }
        __syncthreads();
    }

    const int w = tid >> 5;
    const int lane = tid & 31;
    float mx = -CUDART_INF_F;
    for (int n = lane; n < N_; n += 32) mx = fmaxf(mx, lg_s[w][n]);
#pragma unroll
    for (int off = 16; off > 0; off >>= 1)
        mx = fmaxf(mx, __shfl_xor_sync(0xffffffffu, mx, off));
    float sum = 0.f;
    for (int n = lane; n < N_; n += 32) {
        float e = __expf(lg_s[w][n] - mx);
        lg_s[w][n] = e;
        sum += e;
    }
#pragma unroll
    for (int off = 16; off > 0; off >>= 1)
        sum += __shfl_xor_sync(0xffffffffu, sum, off);
    float inv = 1.f / sum;
    for (int n = lane; n < N_; n += 32)
        out[(size_t)(row0 + w) * N_ + n] = lg_s[w][n] * inv;
}

// ---------------------------------------------------------------------------
// Host: launch pipeline (graph-capturable, allocation-free)
// ---------------------------------------------------------------------------
extern "C" void kernel_launch(void* const* d_in, const int* in_sizes, int n_in,
                              void* d_out, int out_size)
{
    const float* enc  = (const float*)d_in[0];
    const float* dist = (const float*)d_in[1];
    const float* mask = (const float*)d_in[2];
    const int*   cur  = (const int*)d_in[3];
    const float* Wq   = (const float*)d_in[4];
    const float* Wk   = (const float*)d_in[5];
    const float* Wv   = (const float*)d_in[6];
    const float* Wmhc = (const float*)d_in[7];
    const float* bmhc = (const float*)d_in[8];
    const float* W1   = (const float*)d_in[9];
    const float* b1   = (const float*)d_in[10];
    const float* W2   = (const float*)d_in[11];
    const float* b2   = (const float*)d_in[12];
    float* out = (float*)d_out;

    float *p_qin, *p_q, *p_kv, *p_att, *p_mh, *p_Wkv;
    __nv_bfloat16 *p_bfh, *p_bfl, *p_h1h, *p_h1l, *p_w1h, *p_w1l, *p_w2h, *p_w2l;
    cudaGetSymbolAddress((void**)&p_qin,  g_qin);
    cudaGetSymbolAddress((void**)&p_q,    g_q);
    cudaGetSymbolAddress((void**)&p_kv,   g_kv);
    cudaGetSymbolAddress((void**)&p_att,  g_att);
    cudaGetSymbolAddress((void**)&p_mh,   g_mh);
    cudaGetSymbolAddress((void**)&p_Wkv,  g_Wkv);
    cudaGetSymbolAddress((void**)&p_bfh,  g_bflat_h);
    cudaGetSymbolAddress((void**)&p_bfl,  g_bflat_l);
    cudaGetSymbolAddress((void**)&p_h1h,  g_h1_h);
    cudaGetSymbolAddress((void**)&p_h1l,  g_h1_l);
    cudaGetSymbolAddress((void**)&p_w1h,  g_w1t_h);
    cudaGetSymbolAddress((void**)&p_w1l,  g_w1t_l);
    cudaGetSymbolAddress((void**)&p_w2h,  g_w2t_h);
    cudaGetSymbolAddress((void**)&p_w2l,  g_w2t_l);

    knn_kernel<<<ROWS_ / 8, 256>>>(dist, mask, cur);
    gather_kernel<<<ROWS_, 128>>>(enc, cur);
    pack_kv_kernel<<<(D_ * 2 * D_ + 255) / 256, 256>>>(Wk, Wv);
    pack_w_kernel<<<(KNN_ * D_ * 5 * D_ + 255) / 256, 256>>>(W1, p_w1h, p_w1l,
                                                             KNN_ * D_, 5 * D_);
    pack_w_kernel<<<(5 * D_ * D_ + 255) / 256, 256>>>(W2, p_w2h, p_w2l,
                                                      5 * D_, D_);

    // kv = enc @ [Wk|Wv] : M=6400, N=256, K=128
    gemm2_kernel<<<dim3(4, 100), 256>>>(enc, p_Wkv, nullptr, p_kv,
                                        2 * D_, D_, D_, 2 * D_, 0);
    // h1 = relu(bflat @ W1 + b1) : tensor-core split-bf16, out split-bf16
    mma_gemm_kernel<1, 1><<<dim3(5, 50), 256>>>(
        p_bfh, p_bfl, p_w1h, p_w1l, b1,
        nullptr, p_h1h, p_h1l, KNN_ * D_, 5 * D_);
    // unv = h1 @ W2 + b2 -> qin[:,128:256] : tensor-core, fp32 out (ldc=256)
    mma_gemm_kernel<0, 0><<<dim3(1, 50), 256>>>(
        p_h1h, p_h1l, p_w2h, p_w2l, b2,
        p_qin + D_, nullptr, nullptr, 5 * D_, 2 * D_);
    // q = qin @ Wq : M=6400, N=128, K=256
    gemm2_kernel<<<dim3(2, 100), 256>>>(p_qin, Wq, nullptr, p_q,
                                        D_, 2 * D_, 2 * D_, D_, 0);

    attn_kernel<<<dim3(25, H_, B_), 128>>>(mask);

    // mh = att @ Wmhc + bmhc : M=6400, N=128, K=128
    gemm2_kernel<<<dim3(2, 100), 256>>>(p_att, Wmhc, bmhc, p_mh,
                                        D_, D_, D_, D_, 0);

    final_kernel<<<ROWS_ / 8, 256>>>(enc, mask, out);
}

// round 7
// speedup vs baseline: 5.4644x; 1.1374x over previous
#include <cuda_runtime.h>
#include <cuda_bf16.h>
#include <math_constants.h>
#include <math.h>

// Problem constants
#define B_    32
#define R_    200
#define N_    200
#define D_    128
#define H_    8
#define QK_   16
#define KNN_  10
#define CLIP_ 10.0f
#define ROWS_    (B_ * R_)   // 6400 decoder rows

// ---------------------------------------------------------------------------
// Scratch (device globals — no allocation allowed)
// ---------------------------------------------------------------------------
__device__ __nv_bfloat16 g_bflat_h[(size_t)ROWS_ * KNN_ * D_];  // [6400,1280]
__device__ __nv_bfloat16 g_bflat_l[(size_t)ROWS_ * KNN_ * D_];
__device__ __nv_bfloat16 g_h1_h[(size_t)ROWS_ * 5 * D_];        // [6400,640]
__device__ __nv_bfloat16 g_h1_l[(size_t)ROWS_ * 5 * D_];
__device__ __nv_bfloat16 g_w1t_h[(size_t)5 * D_ * KNN_ * D_];   // [640,1280] (transposed)
__device__ __nv_bfloat16 g_w1t_l[(size_t)5 * D_ * KNN_ * D_];
__device__ __nv_bfloat16 g_w2t_h[(size_t)D_ * 5 * D_];          // [128,640]
__device__ __nv_bfloat16 g_w2t_l[(size_t)D_ * 5 * D_];
__device__ float g_qin[(size_t)ROWS_ * 2 * D_];       // [6400,256] = [cur | unv]
__device__ float g_q[(size_t)ROWS_ * D_];
__device__ float g_kv[(size_t)ROWS_ * 2 * D_];        // [b*N+n][0:128 k | 128:256 v]
__device__ float g_att[(size_t)ROWS_ * D_];
__device__ float g_mh[(size_t)ROWS_ * D_];
__device__ float g_Wkv[(size_t)D_ * 2 * D_];          // [128][256] = [Wk | Wv]
__device__ int   g_knn[(size_t)ROWS_ * KNN_];

// ---------------------------------------------------------------------------
// 1) kNN: warp per row.
// ---------------------------------------------------------------------------
__global__ void __launch_bounds__(256)
knn_kernel(const float* __restrict__ distance,
           const float* __restrict__ ninf,
           const int* __restrict__ current)
{
    const int w = threadIdx.x >> 5;
    const int lane = threadIdx.x & 31;
    const int row = blockIdx.x * 8 + w;
    if (row >= ROWS_) return;
    const int b = row / R_;
    const int cur = current[row];
    const float* dist = distance + ((size_t)b * N_ + cur) * N_;
    const float* mp = ninf + (size_t)row * N_;

    float v[7];
#pragma unroll
    for (int i = 0; i < 7; i++) {
        int n = lane + 32 * i;
        if (n < N_) {
            float m = mp[n];
            v[i] = isinf(m) ? CUDART_INF_F : dist[n];
        } else {
            v[i] = CUDART_INF_F;
        }
    }

#pragma unroll
    for (int j = 0; j < KNN_; j++) {
        float bv = v[0]; int bi = lane;
#pragma unroll
        for (int i = 1; i < 7; i++) {
            if (v[i] < bv) { bv = v[i]; bi = lane + 32 * i; }
        }
#pragma unroll
        for (int off = 16; off > 0; off >>= 1) {
            float ov = __shfl_xor_sync(0xffffffffu, bv, off);
            int   oi = __shfl_xor_sync(0xffffffffu, bi, off);
            if (ov < bv || (ov == bv && oi < bi)) { bv = ov; bi = oi; }
        }
        int sel = isinf(bv) ? N_ : bi;
        if (lane == j) g_knn[(size_t)row * KNN_ + j] = sel;
        if (!isinf(bv) && (bi & 31) == lane) v[bi >> 5] = CUDART_INF_F;
    }
}

// ---------------------------------------------------------------------------
// 2) gather + pad-avg -> bflat (bf16 hi/lo) ; current embedding -> qin[:,0:128]
// ---------------------------------------------------------------------------
__global__ void gather_kernel(const float* __restrict__ enc,
                              const int* __restrict__ current)
{
    int row = blockIdx.x;
    int b = row / R_;
    int d = threadIdx.x;  // 128
    __shared__ int sid[KNN_];
    __shared__ int scnt;
    if (d < KNN_) sid[d] = g_knn[(size_t)row * KNN_ + d];
    __syncthreads();
    if (d == 0) {
        int c = 0;
#pragma unroll
        for (int j = 0; j < KNN_; j++) c += (sid[j] < N_);
        scnt = c;
    }
    __syncthreads();

    float v[KNN_];
    float sum = 0.f;
#pragma unroll
    for (int j = 0; j < KNN_; j++) {
        int id = sid[j];
        float x = (id < N_) ? enc[((size_t)b * N_ + id) * D_ + d] : 0.f;
        v[j] = x; sum += x;
    }
    float mean = sum / fmaxf((float)scnt, 1e-9f);
#pragma unroll
    for (int j = 0; j < KNN_; j++) {
        float x = (sid[j] < N_) ? v[j] : mean;
        __nv_bfloat16 hi = __float2bfloat16_rn(x);
        __nv_bfloat16 lo = __float2bfloat16_rn(x - __bfloat162float(hi));
        size_t o = (size_t)row * (KNN_ * D_) + j * D_ + d;
        g_bflat_h[o] = hi;
        g_bflat_l[o] = lo;
    }

    int cur = current[row];
    g_qin[(size_t)row * (2 * D_) + d] = enc[((size_t)b * N_ + cur) * D_ + d];
}

// ---------------------------------------------------------------------------
// pack [Wk | Wv] -> g_Wkv [128][256]
// ---------------------------------------------------------------------------
__global__ void pack_kv_kernel(const float* __restrict__ Wk,
                               const float* __restrict__ Wv)
{
    int i = blockIdx.x * blockDim.x + threadIdx.x;
    if (i >= D_ * 2 * D_) return;
    int k = i / (2 * D_);
    int n = i % (2 * D_);
    g_Wkv[i] = (n < D_) ? Wk[(size_t)k * D_ + n] : Wv[(size_t)k * D_ + (n - D_)];
}

// ---------------------------------------------------------------------------
// Tiled transpose + bf16 split: W[K][N] -> T_hi/T_lo [N][K]. 32x32 tiles,
// block (32,8). K, N multiples of 32. Coalesced both sides.
// ---------------------------------------------------------------------------
__global__ void pack_wT_kernel(const float* __restrict__ W,
                               __nv_bfloat16* __restrict__ Th,
                               __nv_bfloat16* __restrict__ Tl,
                               int K, int Nd)
{
    __shared__ float tile[32][33];
    const int k0 = blockIdx.x * 32;
    const int n0 = blockIdx.y * 32;
    const int tx = threadIdx.x;
    const int ty = threadIdx.y;
#pragma unroll
    for (int j = 0; j < 4; j++)
        tile[ty + 8 * j][tx] = W[(size_t)(k0 + ty + 8 * j) * Nd + n0 + tx];
    __syncthreads();
#pragma unroll
    for (int j = 0; j < 4; j++) {
        float x = tile[tx][ty + 8 * j];
        __nv_bfloat16 hi = __float2bfloat16_rn(x);
        size_t o = (size_t)(n0 + ty + 8 * j) * K + k0 + tx;
        Th[o] = hi;
        Tl[o] = __float2bfloat16_rn(x - __bfloat162float(hi));
    }
}

// ---------------------------------------------------------------------------
// ldmatrix helper
// ---------------------------------------------------------------------------
#define LDMX4(r0, r1, r2, r3, addr)                                         \
    asm volatile("ldmatrix.sync.aligned.m8n8.x4.shared.b16 "                \
                 "{%0,%1,%2,%3}, [%4];"                                     \
                 : "=r"(r0), "=r"(r1), "=r"(r2), "=r"(r3) : "r"(addr))

#define MMA_BF16(cc, a0, a1, a2, a3, b0, b1)                                \
    asm volatile("mma.sync.aligned.m16n8k16.row.col.f32.bf16.bf16.f32 "     \
                 "{%0,%1,%2,%3},{%4,%5,%6,%7},{%8,%9},{%0,%1,%2,%3};"       \
                 : "+f"(cc[0]), "+f"(cc[1]), "+f"(cc[2]), "+f"(cc[3])       \
                 : "r"(a0), "r"(a1), "r"(a2), "r"(a3), "r"(b0), "r"(b1))

// ---------------------------------------------------------------------------
// Split-bf16 tensor GEMM with ldmatrix: C = A @ B^T (+bias).
// A=[M,K] hi/lo bf16 k-major; B=[N,K] hi/lo bf16 k-major.
// Block 128x128, BK=16, 8 warps (64x32). 3 HMMA passes (hh, hl, lh).
// smem row layout (80 B stride, conflict-free ldmatrix):
//   words 0-7: hi k0-15, words 8-15: lo k0-15, words 16-19: pad
// ---------------------------------------------------------------------------
template <int RELU, int SPLIT_OUT>
__global__ void __launch_bounds__(256, 2)
mma_gemm_kernel(const __nv_bfloat16* __restrict__ Ah,
                const __nv_bfloat16* __restrict__ Al,
                const __nv_bfloat16* __restrict__ Bh,
                const __nv_bfloat16* __restrict__ Bl,
                const float* __restrict__ bias,
                float* __restrict__ Cf,
                __nv_bfloat16* __restrict__ Ch,
                __nv_bfloat16* __restrict__ Cl,
                int Kd, int ldc)
{
    __shared__ unsigned As[2][128][20];
    __shared__ unsigned Bs[2][128][20];

    const int tid = threadIdx.x;
    const int lane = tid & 31;
    const int wid = tid >> 5;
    const int wm = (wid & 1) * 64;
    const int wn = (wid >> 1) * 32;
    const int row0 = blockIdx.y * 128;
    const int col0 = blockIdx.x * 128;

    // loader mapping: thread -> (row, k-half), one uint4 (8 bf16) per array
    const int l_r = tid >> 1;
    const int l_h = tid & 1;
    const size_t a_base = (size_t)(row0 + l_r) * Kd + l_h * 8;
    const size_t b_base = (size_t)(col0 + l_r) * Kd + l_h * 8;

    const unsigned as0 = (unsigned)__cvta_generic_to_shared(&As[0][0][0]);
    const unsigned bs0 = (unsigned)__cvta_generic_to_shared(&Bs[0][0][0]);
    const unsigned BUFB = 128 * 20 * 4;   // bytes per buffer

    // ldmatrix per-lane offsets (bytes), hi; lo = +32
    const unsigned a_lm = (unsigned)((lane & 15) * 80 + (lane >> 4) * 16);
    const unsigned b_lm = (unsigned)(((lane & 7) + ((lane >> 4) << 3)) * 80 +
                                     ((lane >> 3) & 1) * 16);

    const int TILES = Kd / 16;

    uint4 pah, pal, pbh, pbl;
    pah = *(const uint4*)&Ah[a_base];
    pal = *(const uint4*)&Al[a_base];
    pbh = *(const uint4*)&Bh[b_base];
    pbl = *(const uint4*)&Bl[b_base];
    {
        *(uint4*)&As[0][l_r][l_h * 4] = pah;
        *(uint4*)&As[0][l_r][8 + l_h * 4] = pal;
        *(uint4*)&Bs[0][l_r][l_h * 4] = pbh;
        *(uint4*)&Bs[0][l_r][8 + l_h * 4] = pbl;
    }
    __syncthreads();

    float c[4][4][4];
#pragma unroll
    for (int i = 0; i < 4; i++)
#pragma unroll
        for (int j = 0; j < 4; j++)
#pragma unroll
            for (int r = 0; r < 4; r++) c[i][j][r] = 0.f;

    for (int t = 0; t < TILES; t++) {
        const int buf = t & 1;
        const unsigned bof = buf * BUFB;
        if (t + 1 < TILES) {
            const size_t ko = (size_t)(t + 1) * 16;
            pah = *(const uint4*)&Ah[a_base + ko];
            pal = *(const uint4*)&Al[a_base + ko];
            pbh = *(const uint4*)&Bh[b_base + ko];
            pbl = *(const uint4*)&Bl[b_base + ko];
        }

        // B fragments: 4 n-tiles x {b0,b1} x {hi,lo} via 4 ldmatrix.x4
        unsigned bh[4][2], bl[4][2];
#pragma unroll
        for (int np = 0; np < 2; np++) {
            unsigned addr = bs0 + bof + (wn + np * 16) * 80 + b_lm;
            LDMX4(bh[2 * np][0], bh[2 * np][1],
                  bh[2 * np + 1][0], bh[2 * np + 1][1], addr);
            LDMX4(bl[2 * np][0], bl[2 * np][1],
                  bl[2 * np + 1][0], bl[2 * np + 1][1], addr + 32);
        }

#pragma unroll
        for (int mt = 0; mt < 4; mt++) {
            unsigned aaddr = as0 + bof + (wm + mt * 16) * 80 + a_lm;
            unsigned ah0, ah1, ah2, ah3, al0, al1, al2, al3;
            LDMX4(ah0, ah1, ah2, ah3, aaddr);
            LDMX4(al0, al1, al2, al3, aaddr + 32);
#pragma unroll
            for (int nt = 0; nt < 4; nt++) {
                float* cc = c[mt][nt];
                MMA_BF16(cc, ah0, ah1, ah2, ah3, bh[nt][0], bh[nt][1]);
                MMA_BF16(cc, ah0, ah1, ah2, ah3, bl[nt][0], bl[nt][1]);
                MMA_BF16(cc, al0, al1, al2, al3, bh[nt][0], bh[nt][1]);
            }
        }

        if (t + 1 < TILES) {
            const int nb = buf ^ 1;
            *(uint4*)&As[nb][l_r][l_h * 4] = pah;
            *(uint4*)&As[nb][l_r][8 + l_h * 4] = pal;
            *(uint4*)&Bs[nb][l_r][l_h * 4] = pbh;
            *(uint4*)&Bs[nb][l_r][8 + l_h * 4] = pbl;
        }
        __syncthreads();
    }

    // epilogue
    const int g = lane >> 2;
    const int kp = lane & 3;
#pragma unroll
    for (int mt = 0; mt < 4; mt++) {
#pragma unroll
        for (int nt = 0; nt < 4; nt++) {
            const int row = row0 + wm + mt * 16 + g;
            const int col = col0 + wn + nt * 8 + 2 * kp;
            float b0 = bias ? bias[col] : 0.f;
            float b1 = bias ? bias[col + 1] : 0.f;
            float v00 = c[mt][nt][0] + b0, v01 = c[mt][nt][1] + b1;
            float v10 = c[mt][nt][2] + b0, v11 = c[mt][nt][3] + b1;
            if (RELU) {
                v00 = fmaxf(v00, 0.f); v01 = fmaxf(v01, 0.f);
                v10 = fmaxf(v10, 0.f); v11 = fmaxf(v11, 0.f);
            }
            if (SPLIT_OUT) {
                __nv_bfloat16 h00 = __float2bfloat16_rn(v00);
                __nv_bfloat16 h01 = __float2bfloat16_rn(v01);
                __nv_bfloat16 h10 = __float2bfloat16_rn(v10);
                __nv_bfloat16 h11 = __float2bfloat16_rn(v11);
                __nv_bfloat162 hp0 = {h00, h01};
                __nv_bfloat162 hp1 = {h10, h11};
                __nv_bfloat162 lp0 = {__float2bfloat16_rn(v00 - __bfloat162float(h00)),
                                      __float2bfloat16_rn(v01 - __bfloat162float(h01))};
                __nv_bfloat162 lp1 = {__float2bfloat16_rn(v10 - __bfloat162float(h10)),
                                      __float2bfloat16_rn(v11 - __bfloat162float(h11))};
                *(__nv_bfloat162*)&Ch[(size_t)row * ldc + col] = hp0;
                *(__nv_bfloat162*)&Ch[(size_t)(row + 8) * ldc + col] = hp1;
                *(__nv_bfloat162*)&Cl[(size_t)row * ldc + col] = lp0;
                *(__nv_bfloat162*)&Cl[(size_t)(row + 8) * ldc + col] = lp1;
            } else {
                float2 f0 = {v00, v01};
                float2 f1 = {v10, v11};
                *(float2*)&Cf[(size_t)row * ldc + col] = f0;
                *(float2*)&Cf[(size_t)(row + 8) * ldc + col] = f1;
            }
        }
    }
}

// ---------------------------------------------------------------------------
// Double-buffered fp32 GEMM (small GEMMs: kv / q / mhc)
// ---------------------------------------------------------------------------
__global__ void __launch_bounds__(256, 4)
gemm2_kernel(const float* __restrict__ A, const float* __restrict__ W,
             const float* __restrict__ bias, float* __restrict__ C,
             int Nd, int Kd, int lda, int ldc, int relu)
{
    constexpr int BM = 64, BN = 64, BK = 16;
    __shared__ float As[2][BK][BM + 4];
    __shared__ float Bs[2][BK][BN + 4];

    const int tid = threadIdx.x;
    const int tx = tid & 15;
    const int ty = tid >> 4;
    const int row0 = blockIdx.y * BM;
    const int col0 = blockIdx.x * BN;

    const int am = tid >> 2;
    const int ak = (tid & 3) * 4;
    const int bk = tid >> 4;
    const int bn = (tid & 15) * 4;

    const int TILES = Kd / BK;

    float4 ra, rb;
    ra = *(const float4*)&A[(size_t)(row0 + am) * lda + ak];
    rb = *(const float4*)&W[(size_t)bk * Nd + col0 + bn];
    As[0][ak + 0][am] = ra.x; As[0][ak + 1][am] = ra.y;
    As[0][ak + 2][am] = ra.z; As[0][ak + 3][am] = ra.w;
    *(float4*)&Bs[0][bk][bn] = rb;
    __syncthreads();

    float acc[4][4];
#pragma unroll
    for (int i = 0; i < 4; i++)
#pragma unroll
        for (int j = 0; j < 4; j++) acc[i][j] = 0.f;

    for (int t = 0; t < TILES; t++) {
        int buf = t & 1;
        if (t + 1 < TILES) {
            ra = *(const float4*)&A[(size_t)(row0 + am) * lda + (t + 1) * BK + ak];
            rb = *(const float4*)&W[(size_t)((t + 1) * BK + bk) * Nd + col0 + bn];
        }
#pragma unroll
        for (int kk = 0; kk < BK; kk++) {
            float4 av = *(const float4*)&As[buf][kk][ty * 4];
            float4 bv = *(const float4*)&Bs[buf][kk][tx * 4];
            float a[4] = {av.x, av.y, av.z, av.w};
            float b[4] = {bv.x, bv.y, bv.z, bv.w};
#pragma unroll
            for (int i = 0; i < 4; i++)
#pragma unroll
                for (int j = 0; j < 4; j++) acc[i][j] += a[i] * b[j];
        }
        if (t + 1 < TILES) {
            int nb = buf ^ 1;
            As[nb][ak + 0][am] = ra.x; As[nb][ak + 1][am] = ra.y;
            As[nb][ak + 2][am] = ra.z; As[nb][ak + 3][am] = ra.w;
            *(float4*)&Bs[nb][bk][bn] = rb;
        }
        __syncthreads();
    }

    float bs[4] = {0.f, 0.f, 0.f, 0.f};
    if (bias) {
#pragma unroll
        for (int j = 0; j < 4; j++) bs[j] = bias[col0 + tx * 4 + j];
    }
#pragma unroll
    for (int i = 0; i < 4; i++) {
        int gm = row0 + ty * 4 + i;
        float4 r;
        float rr[4];
#pragma unroll
        for (int j = 0; j < 4; j++) {
            float x = acc[i][j] + bs[j];
            rr[j] = relu ? fmaxf(x, 0.f) : x;
        }
        r.x = rr[0]; r.y = rr[1]; r.z = rr[2]; r.w = rr[3];
        *(float4*)&C[(size_t)gm * ldc + col0 + tx * 4] = r;
    }
}

// ---------------------------------------------------------------------------
// Attention: block per (b, h, 8-row tile). 128 threads.
// ---------------------------------------------------------------------------
__global__ void __launch_bounds__(128, 4)
attn_kernel(const float* __restrict__ ninf)
{
    __shared__ float q_s[8][QK_];
    __shared__ float k_s[QK_][N_ + 8];
    __shared__ float v_s[N_][QK_];
    __shared__ float w_s[8][N_];

    const int rtile = blockIdx.x;
    const int h = blockIdx.y;
    const int b = blockIdx.z;
    const int row0 = b * R_ + rtile * 8;
    const int tid = threadIdx.x;
    const int w = tid >> 5;
    const int lane = tid & 31;

    if (tid < 8 * QK_) {
        int rl = tid >> 4, d = tid & 15;
        q_s[rl][d] = g_q[(size_t)(row0 + rl) * D_ + h * QK_ + d];
    }
    const float* kvb = g_kv + (size_t)b * N_ * (2 * D_) + h * QK_;
    for (int idx = tid; idx < N_ * QK_; idx += 128) {
        int n = idx >> 4, d = idx & 15;
        k_s[d][n] = kvb[(size_t)n * (2 * D_) + d];
        v_s[n][d] = kvb[(size_t)n * (2 * D_) + D_ + d];
    }
    __syncthreads();

#pragma unroll
    for (int rr = 0; rr < 2; rr++) {
        int rl = w * 2 + rr;
        int row = row0 + rl;
        const float* maskp = ninf + (size_t)row * N_;

        float mx = -CUDART_INF_F;
        for (int n0 = 0; n0 < N_; n0 += 32) {
            int n = n0 + lane;
            float s = -CUDART_INF_F;
            if (n < N_) {
                float a = 0.f;
#pragma unroll
                for (int d = 0; d < QK_; d++) a += q_s[rl][d] * k_s[d][n];
                s = a * 0.25f + maskp[n];
                w_s[rl][n] = s;
            }
            mx = fmaxf(mx, s);
        }
#pragma unroll
        for (int off = 16; off > 0; off >>= 1)
            mx = fmaxf(mx, __shfl_xor_sync(0xffffffffu, mx, off));

        float sum = 0.f;
        for (int n0 = 0; n0 < N_; n0 += 32) {
            int n = n0 + lane;
            if (n < N_) {
                float e = __expf(w_s[rl][n] - mx);
                w_s[rl][n] = e;
                sum += e;
            }
        }
#pragma unroll
        for (int off = 16; off > 0; off >>= 1)
            sum += __shfl_xor_sync(0xffffffffu, sum, off);
        float inv = 1.f / sum;
        __syncwarp();

        int d = lane & 15;
        int half = lane >> 4;
        float acc = 0.f;
#pragma unroll 2
        for (int n = half; n < N_; n += 2)
            acc += w_s[rl][n] * v_s[n][d];
        acc += __shfl_xor_sync(0xffffffffu, acc, 16);
        if (lane < QK_)
            g_att[(size_t)row * D_ + h * QK_ + d] = acc * inv;
        __syncwarp();
    }
}

// ---------------------------------------------------------------------------
// Final: block per 8-row tile.
// ---------------------------------------------------------------------------
__global__ void __launch_bounds__(256, 4)
final_kernel(const float* __restrict__ enc,
             const float* __restrict__ ninf,
             float* __restrict__ out)
{
    __shared__ float mh_s[8][D_];
    __shared__ float enc_s[32][D_ + 4];
    __shared__ float lg_s[8][N_];

    const int row0 = blockIdx.x * 8;
    const int b = row0 / R_;
    const int tid = threadIdx.x;

    {
        int r = tid >> 5, dw = tid & 31;
        *(float4*)&mh_s[r][dw * 4] =
            *(const float4*)&g_mh[(size_t)(row0 + r) * D_ + dw * 4];
    }
    __syncthreads();

    const int r = tid >> 5;
    const int nl = tid & 31;
    const float* encb = enc + (size_t)b * N_ * D_;

    for (int n0 = 0; n0 < N_; n0 += 32) {
        int nrem = N_ - n0; if (nrem > 32) nrem = 32;
        for (int v = tid; v < 32 * 32; v += 256) {
            int n = v >> 5, dw = v & 31;
            if (n < nrem)
                *(float4*)&enc_s[n][dw * 4] =
                    *(const float4*)&encb[(size_t)(n0 + n) * D_ + dw * 4];
        }
        __syncthreads();
        if (nl < nrem) {
            float acc = 0.f;
#pragma unroll
            for (int d = 0; d < D_; d += 4) {
                float4 m4 = *(const float4*)&mh_s[r][d];
                float4 e4 = *(const float4*)&enc_s[nl][d];
                acc += m4.x * e4.x + m4.y * e4.y + m4.z * e4.z + m4.w * e4.w;
            }
            float sh = acc * 0.08838834764831845f;
            lg_s[r][n0 + nl] = CLIP_ * tanhf(sh)
                             + ninf[(size_t)(row0 + r) * N_ + n0 + nl];
        }
        __syncthreads();
    }

    const int w = tid >> 5;
    const int lane = tid & 31;
    float mx = -CUDART_INF_F;
    for (int n = lane; n < N_; n += 32) mx = fmaxf(mx, lg_s[w][n]);
#pragma unroll
    for (int off = 16; off > 0; off >>= 1)
        mx = fmaxf(mx, __shfl_xor_sync(0xffffffffu, mx, off));
    float sum = 0.f;
    for (int n = lane; n < N_; n += 32) {
        float e = __expf(lg_s[w][n] - mx);
        lg_s[w][n] = e;
        sum += e;
    }
#pragma unroll
    for (int off = 16; off > 0; off >>= 1)
        sum += __shfl_xor_sync(0xffffffffu, sum, off);
    float inv = 1.f / sum;
    for (int n = lane; n < N_; n += 32)
        out[(size_t)(row0 + w) * N_ + n] = lg_s[w][n] * inv;
}

// ---------------------------------------------------------------------------
// Host: launch pipeline (graph-capturable, allocation-free)
// ---------------------------------------------------------------------------
extern "C" void kernel_launch(void* const* d_in, const int* in_sizes, int n_in,
                              void* d_out, int out_size)
{
    const float* enc  = (const float*)d_in[0];
    const float* dist = (const float*)d_in[1];
    const float* mask = (const float*)d_in[2];
    const int*   cur  = (const int*)d_in[3];
    const float* Wq   = (const float*)d_in[4];
    const float* Wk   = (const float*)d_in[5];
    const float* Wv   = (const float*)d_in[6];
    const float* Wmhc = (const float*)d_in[7];
    const float* bmhc = (const float*)d_in[8];
    const float* W1   = (const float*)d_in[9];
    const float* b1   = (const float*)d_in[10];
    const float* W2   = (const float*)d_in[11];
    const float* b2   = (const float*)d_in[12];
    float* out = (float*)d_out;

    float *p_qin, *p_q, *p_kv, *p_att, *p_mh, *p_Wkv;
    __nv_bfloat16 *p_bfh, *p_bfl, *p_h1h, *p_h1l, *p_w1h, *p_w1l, *p_w2h, *p_w2l;
    cudaGetSymbolAddress((void**)&p_qin,  g_qin);
    cudaGetSymbolAddress((void**)&p_q,    g_q);
    cudaGetSymbolAddress((void**)&p_kv,   g_kv);
    cudaGetSymbolAddress((void**)&p_att,  g_att);
    cudaGetSymbolAddress((void**)&p_mh,   g_mh);
    cudaGetSymbolAddress((void**)&p_Wkv,  g_Wkv);
    cudaGetSymbolAddress((void**)&p_bfh,  g_bflat_h);
    cudaGetSymbolAddress((void**)&p_bfl,  g_bflat_l);
    cudaGetSymbolAddress((void**)&p_h1h,  g_h1_h);
    cudaGetSymbolAddress((void**)&p_h1l,  g_h1_l);
    cudaGetSymbolAddress((void**)&p_w1h,  g_w1t_h);
    cudaGetSymbolAddress((void**)&p_w1l,  g_w1t_l);
    cudaGetSymbolAddress((void**)&p_w2h,  g_w2t_h);
    cudaGetSymbolAddress((void**)&p_w2l,  g_w2t_l);

    knn_kernel<<<ROWS_ / 8, 256>>>(dist, mask, cur);
    gather_kernel<<<ROWS_, 128>>>(enc, cur);
    pack_kv_kernel<<<(D_ * 2 * D_ + 255) / 256, 256>>>(Wk, Wv);
    pack_wT_kernel<<<dim3(KNN_ * D_ / 32, 5 * D_ / 32), dim3(32, 8)>>>(
        W1, p_w1h, p_w1l, KNN_ * D_, 5 * D_);
    pack_wT_kernel<<<dim3(5 * D_ / 32, D_ / 32), dim3(32, 8)>>>(
        W2, p_w2h, p_w2l, 5 * D_, D_);

    // kv = enc @ [Wk|Wv] : M=6400, N=256, K=128
    gemm2_kernel<<<dim3(4, 100), 256>>>(enc, p_Wkv, nullptr, p_kv,
                                        2 * D_, D_, D_, 2 * D_, 0);
    // h1 = relu(bflat @ W1 + b1) : tensor-core split-bf16 (ldmatrix)
    mma_gemm_kernel<1, 1><<<dim3(5, 50), 256>>>(
        p_bfh, p_bfl, p_w1h, p_w1l, b1,
        nullptr, p_h1h, p_h1l, KNN_ * D_, 5 * D_);
    // unv = h1 @ W2 + b2 -> qin[:,128:256] : tensor-core, fp32 out (ldc=256)
    mma_gemm_kernel<0, 0><<<dim3(1, 50), 256>>>(
        p_h1h, p_h1l, p_w2h, p_w2l, b2,
        p_qin + D_, nullptr, nullptr, 5 * D_, 2 * D_);
    // q = qin @ Wq : M=6400, N=128, K=256
    gemm2_kernel<<<dim3(2, 100), 256>>>(p_qin, Wq, nullptr, p_q,
                                        D_, 2 * D_, 2 * D_, D_, 0);

    attn_kernel<<<dim3(25, H_, B_), 128>>>(mask);

    // mh = att @ Wmhc + bmhc : M=6400, N=128, K=128
    gemm2_kernel<<<dim3(2, 100), 256>>>(p_att, Wmhc, bmhc, p_mh,
                                        D_, D_, D_, D_, 0);

    final_kernel<<<ROWS_ / 8, 256>>>(enc, mask, out);
}

// round 8
// speedup vs baseline: 5.4753x; 1.0020x over previous
#include <cuda_runtime.h>
#include <cuda_bf16.h>
#include <math_constants.h>
#include <math.h>

// Problem constants
#define B_    32
#define R_    200
#define N_    200
#define D_    128
#define H_    8
#define QK_   16
#define KNN_  10
#define CLIP_ 10.0f
#define ROWS_    (B_ * R_)   // 6400 decoder rows

// ---------------------------------------------------------------------------
// Scratch (device globals — no allocation allowed)
// ---------------------------------------------------------------------------
__device__ __nv_bfloat16 g_bflat_h[(size_t)ROWS_ * KNN_ * D_];  // [6400,1280]
__device__ __nv_bfloat16 g_bflat_l[(size_t)ROWS_ * KNN_ * D_];
__device__ __nv_bfloat16 g_h1_h[(size_t)ROWS_ * 5 * D_];        // [6400,640]
__device__ __nv_bfloat16 g_h1_l[(size_t)ROWS_ * 5 * D_];
__device__ __nv_bfloat16 g_w1t_h[(size_t)5 * D_ * KNN_ * D_];   // [640,1280] (transposed)
__device__ __nv_bfloat16 g_w1t_l[(size_t)5 * D_ * KNN_ * D_];
__device__ __nv_bfloat16 g_w2t_h[(size_t)D_ * 5 * D_];          // [128,640]
__device__ __nv_bfloat16 g_w2t_l[(size_t)D_ * 5 * D_];
__device__ float g_qin[(size_t)ROWS_ * 2 * D_];       // [6400,256] = [cur | unv]
__device__ float g_q[(size_t)ROWS_ * D_];
__device__ float g_kv[(size_t)ROWS_ * 2 * D_];        // [b*N+n][0:128 k | 128:256 v]
__device__ float g_att[(size_t)ROWS_ * D_];
__device__ float g_mh[(size_t)ROWS_ * D_];
__device__ float g_Wkv[(size_t)D_ * 2 * D_];          // [128][256] = [Wk | Wv]
__device__ int   g_knn[(size_t)ROWS_ * KNN_];

// ---------------------------------------------------------------------------
// 1) kNN: warp per row.
// ---------------------------------------------------------------------------
__global__ void __launch_bounds__(256)
knn_kernel(const float* __restrict__ distance,
           const float* __restrict__ ninf,
           const int* __restrict__ current)
{
    const int w = threadIdx.x >> 5;
    const int lane = threadIdx.x & 31;
    const int row = blockIdx.x * 8 + w;
    if (row >= ROWS_) return;
    const int b = row / R_;
    const int cur = current[row];
    const float* dist = distance + ((size_t)b * N_ + cur) * N_;
    const float* mp = ninf + (size_t)row * N_;

    float v[7];
#pragma unroll
    for (int i = 0; i < 7; i++) {
        int n = lane + 32 * i;
        if (n < N_) {
            float m = mp[n];
            v[i] = isinf(m) ? CUDART_INF_F : dist[n];
        } else {
            v[i] = CUDART_INF_F;
        }
    }

#pragma unroll
    for (int j = 0; j < KNN_; j++) {
        float bv = v[0]; int bi = lane;
#pragma unroll
        for (int i = 1; i < 7; i++) {
            if (v[i] < bv) { bv = v[i]; bi = lane + 32 * i; }
        }
#pragma unroll
        for (int off = 16; off > 0; off >>= 1) {
            float ov = __shfl_xor_sync(0xffffffffu, bv, off);
            int   oi = __shfl_xor_sync(0xffffffffu, bi, off);
            if (ov < bv || (ov == bv && oi < bi)) { bv = ov; bi = oi; }
        }
        int sel = isinf(bv) ? N_ : bi;
        if (lane == j) g_knn[(size_t)row * KNN_ + j] = sel;
        if (!isinf(bv) && (bi & 31) == lane) v[bi >> 5] = CUDART_INF_F;
    }
}

// ---------------------------------------------------------------------------
// 2) gather + pad-avg -> bflat (bf16 hi/lo) ; current embedding -> qin[:,0:128]
// ---------------------------------------------------------------------------
__global__ void gather_kernel(const float* __restrict__ enc,
                              const int* __restrict__ current)
{
    int row = blockIdx.x;
    int b = row / R_;
    int d = threadIdx.x;  // 128
    __shared__ int sid[KNN_];
    __shared__ int scnt;
    if (d < KNN_) sid[d] = g_knn[(size_t)row * KNN_ + d];
    __syncthreads();
    if (d == 0) {
        int c = 0;
#pragma unroll
        for (int j = 0; j < KNN_; j++) c += (sid[j] < N_);
        scnt = c;
    }
    __syncthreads();

    float v[KNN_];
    float sum = 0.f;
#pragma unroll
    for (int j = 0; j < KNN_; j++) {
        int id = sid[j];
        float x = (id < N_) ? enc[((size_t)b * N_ + id) * D_ + d] : 0.f;
        v[j] = x; sum += x;
    }
    float mean = sum / fmaxf((float)scnt, 1e-9f);
#pragma unroll
    for (int j = 0; j < KNN_; j++) {
        float x = (sid[j] < N_) ? v[j] : mean;
        __nv_bfloat16 hi = __float2bfloat16_rn(x);
        __nv_bfloat16 lo = __float2bfloat16_rn(x - __bfloat162float(hi));
        size_t o = (size_t)row * (KNN_ * D_) + j * D_ + d;
        g_bflat_h[o] = hi;
        g_bflat_l[o] = lo;
    }

    int cur = current[row];
    g_qin[(size_t)row * (2 * D_) + d] = enc[((size_t)b * N_ + cur) * D_ + d];
}

// ---------------------------------------------------------------------------
// pack [Wk | Wv] -> g_Wkv [128][256]
// ---------------------------------------------------------------------------
__global__ void pack_kv_kernel(const float* __restrict__ Wk,
                               const float* __restrict__ Wv)
{
    int i = blockIdx.x * blockDim.x + threadIdx.x;
    if (i >= D_ * 2 * D_) return;
    int k = i / (2 * D_);
    int n = i % (2 * D_);
    g_Wkv[i] = (n < D_) ? Wk[(size_t)k * D_ + n] : Wv[(size_t)k * D_ + (n - D_)];
}

// ---------------------------------------------------------------------------
// Tiled transpose + bf16 split: W[K][N] -> T_hi/T_lo [N][K]. 32x32 tiles,
// block (32,8). K, N multiples of 32. Coalesced both sides.
// ---------------------------------------------------------------------------
__global__ void pack_wT_kernel(const float* __restrict__ W,
                               __nv_bfloat16* __restrict__ Th,
                               __nv_bfloat16* __restrict__ Tl,
                               int K, int Nd)
{
    __shared__ float tile[32][33];
    const int k0 = blockIdx.x * 32;
    const int n0 = blockIdx.y * 32;
    const int tx = threadIdx.x;
    const int ty = threadIdx.y;
#pragma unroll
    for (int j = 0; j < 4; j++)
        tile[ty + 8 * j][tx] = W[(size_t)(k0 + ty + 8 * j) * Nd + n0 + tx];
    __syncthreads();
#pragma unroll
    for (int j = 0; j < 4; j++) {
        float x = tile[tx][ty + 8 * j];
        __nv_bfloat16 hi = __float2bfloat16_rn(x);
        size_t o = (size_t)(n0 + ty + 8 * j) * K + k0 + tx;
        Th[o] = hi;
        Tl[o] = __float2bfloat16_rn(x - __bfloat162float(hi));
    }
}

// ---------------------------------------------------------------------------
// ldmatrix helper
// ---------------------------------------------------------------------------
#define LDMX4(r0, r1, r2, r3, addr)                                         \
    asm volatile("ldmatrix.sync.aligned.m8n8.x4.shared.b16 "                \
                 "{%0,%1,%2,%3}, [%4];"                                     \
                 : "=r"(r0), "=r"(r1), "=r"(r2), "=r"(r3) : "r"(addr))

#define MMA_BF16(cc, a0, a1, a2, a3, b0, b1)                                \
    asm volatile("mma.sync.aligned.m16n8k16.row.col.f32.bf16.bf16.f32 "     \
                 "{%0,%1,%2,%3},{%4,%5,%6,%7},{%8,%9},{%0,%1,%2,%3};"       \
                 : "+f"(cc[0]), "+f"(cc[1]), "+f"(cc[2]), "+f"(cc[3])       \
                 : "r"(a0), "r"(a1), "r"(a2), "r"(a3), "r"(b0), "r"(b1))

// ---------------------------------------------------------------------------
// Split-bf16 tensor GEMM with ldmatrix: C = A @ B^T (+bias).
// A=[M,K] hi/lo bf16 k-major; B=[N,K] hi/lo bf16 k-major.
// Block 128x128, BK=16, 8 warps (64x32). 3 HMMA passes (hh, hl, lh).
// smem row layout (80 B stride, conflict-free ldmatrix):
//   words 0-7: hi k0-15, words 8-15: lo k0-15, words 16-19: pad
// ---------------------------------------------------------------------------
template <int RELU, int SPLIT_OUT>
__global__ void __launch_bounds__(256, 2)
mma_gemm_kernel(const __nv_bfloat16* __restrict__ Ah,
                const __nv_bfloat16* __restrict__ Al,
                const __nv_bfloat16* __restrict__ Bh,
                const __nv_bfloat16* __restrict__ Bl,
                const float* __restrict__ bias,
                float* __restrict__ Cf,
                __nv_bfloat16* __restrict__ Ch,
                __nv_bfloat16* __restrict__ Cl,
                int Kd, int ldc)
{
    __shared__ unsigned As[2][128][20];
    __shared__ unsigned Bs[2][128][20];

    const int tid = threadIdx.x;
    const int lane = tid & 31;
    const int wid = tid >> 5;
    const int wm = (wid & 1) * 64;
    const int wn = (wid >> 1) * 32;
    const int row0 = blockIdx.y * 128;
    const int col0 = blockIdx.x * 128;

    // loader mapping: thread -> (row, k-half), one uint4 (8 bf16) per array
    const int l_r = tid >> 1;
    const int l_h = tid & 1;
    const size_t a_base = (size_t)(row0 + l_r) * Kd + l_h * 8;
    const size_t b_base = (size_t)(col0 + l_r) * Kd + l_h * 8;

    const unsigned as0 = (unsigned)__cvta_generic_to_shared(&As[0][0][0]);
    const unsigned bs0 = (unsigned)__cvta_generic_to_shared(&Bs[0][0][0]);
    const unsigned BUFB = 128 * 20 * 4;   // bytes per buffer

    // ldmatrix per-lane offsets (bytes), hi; lo = +32
    const unsigned a_lm = (unsigned)((lane & 15) * 80 + (lane >> 4) * 16);
    const unsigned b_lm = (unsigned)(((lane & 7) + ((lane >> 4) << 3)) * 80 +
                                     ((lane >> 3) & 1) * 16);

    const int TILES = Kd / 16;

    uint4 pah, pal, pbh, pbl;
    pah = *(const uint4*)&Ah[a_base];
    pal = *(const uint4*)&Al[a_base];
    pbh = *(const uint4*)&Bh[b_base];
    pbl = *(const uint4*)&Bl[b_base];
    {
        *(uint4*)&As[0][l_r][l_h * 4] = pah;
        *(uint4*)&As[0][l_r][8 + l_h * 4] = pal;
        *(uint4*)&Bs[0][l_r][l_h * 4] = pbh;
        *(uint4*)&Bs[0][l_r][8 + l_h * 4] = pbl;
    }
    __syncthreads();

    float c[4][4][4];
#pragma unroll
    for (int i = 0; i < 4; i++)
#pragma unroll
        for (int j = 0; j < 4; j++)
#pragma unroll
            for (int r = 0; r < 4; r++) c[i][j][r] = 0.f;

    for (int t = 0; t < TILES; t++) {
        const int buf = t & 1;
        const unsigned bof = buf * BUFB;
        if (t + 1 < TILES) {
            const size_t ko = (size_t)(t + 1) * 16;
            pah = *(const uint4*)&Ah[a_base + ko];
            pal = *(const uint4*)&Al[a_base + ko];
            pbh = *(const uint4*)&Bh[b_base + ko];
            pbl = *(const uint4*)&Bl[b_base + ko];
        }

        // B fragments: 4 n-tiles x {b0,b1} x {hi,lo} via 4 ldmatrix.x4
        unsigned bh[4][2], bl[4][2];
#pragma unroll
        for (int np = 0; np < 2; np++) {
            unsigned addr = bs0 + bof + (wn + np * 16) * 80 + b_lm;
            LDMX4(bh[2 * np][0], bh[2 * np][1],
                  bh[2 * np + 1][0], bh[2 * np + 1][1], addr);
            LDMX4(bl[2 * np][0], bl[2 * np][1],
                  bl[2 * np + 1][0], bl[2 * np + 1][1], addr + 32);
        }

#pragma unroll
        for (int mt = 0; mt < 4; mt++) {
            unsigned aaddr = as0 + bof + (wm + mt * 16) * 80 + a_lm;
            unsigned ah0, ah1, ah2, ah3, al0, al1, al2, al3;
            LDMX4(ah0, ah1, ah2, ah3, aaddr);
            LDMX4(al0, al1, al2, al3, aaddr + 32);
#pragma unroll
            for (int nt = 0; nt < 4; nt++) {
                float* cc = c[mt][nt];
                MMA_BF16(cc, ah0, ah1, ah2, ah3, bh[nt][0], bh[nt][1]);
                MMA_BF16(cc, ah0, ah1, ah2, ah3, bl[nt][0], bl[nt][1]);
                MMA_BF16(cc, al0, al1, al2, al3, bh[nt][0], bh[nt][1]);
            }
        }

        if (t + 1 < TILES) {
            const int nb = buf ^ 1;
            *(uint4*)&As[nb][l_r][l_h * 4] = pah;
            *(uint4*)&As[nb][l_r][8 + l_h * 4] = pal;
            *(uint4*)&Bs[nb][l_r][l_h * 4] = pbh;
            *(uint4*)&Bs[nb][l_r][8 + l_h * 4] = pbl;
        }
        __syncthreads();
    }

    // epilogue
    const int g = lane >> 2;
    const int kp = lane & 3;
#pragma unroll
    for (int mt = 0; mt < 4; mt++) {
#pragma unroll
        for (int nt = 0; nt < 4; nt++) {
            const int row = row0 + wm + mt * 16 + g;
            const int col = col0 + wn + nt * 8 + 2 * kp;
            float b0 = bias ? bias[col] : 0.f;
            float b1 = bias ? bias[col + 1] : 0.f;
            float v00 = c[mt][nt][0] + b0, v01 = c[mt][nt][1] + b1;
            float v10 = c[mt][nt][2] + b0, v11 = c[mt][nt][3] + b1;
            if (RELU) {
                v00 = fmaxf(v00, 0.f); v01 = fmaxf(v01, 0.f);
                v10 = fmaxf(v10, 0.f); v11 = fmaxf(v11, 0.f);
            }
            if (SPLIT_OUT) {
                __nv_bfloat16 h00 = __float2bfloat16_rn(v00);
                __nv_bfloat16 h01 = __float2bfloat16_rn(v01);
                __nv_bfloat16 h10 = __float2bfloat16_rn(v10);
                __nv_bfloat16 h11 = __float2bfloat16_rn(v11);
                __nv_bfloat162 hp0 = {h00, h01};
                __nv_bfloat162 hp1 = {h10, h11};
                __nv_bfloat162 lp0 = {__float2bfloat16_rn(v00 - __bfloat162float(h00)),
                                      __float2bfloat16_rn(v01 - __bfloat162float(h01))};
                __nv_bfloat162 lp1 = {__float2bfloat16_rn(v10 - __bfloat162float(h10)),
                                      __float2bfloat16_rn(v11 - __bfloat162float(h11))};
                *(__nv_bfloat162*)&Ch[(size_t)row * ldc + col] = hp0;
                *(__nv_bfloat162*)&Ch[(size_t)(row + 8) * ldc + col] = hp1;
                *(__nv_bfloat162*)&Cl[(size_t)row * ldc + col] = lp0;
                *(__nv_bfloat162*)&Cl[(size_t)(row + 8) * ldc + col] = lp1;
            } else {
                float2 f0 = {v00, v01};
                float2 f1 = {v10, v11};
                *(float2*)&Cf[(size_t)row * ldc + col] = f0;
                *(float2*)&Cf[(size_t)(row + 8) * ldc + col] = f1;
            }
        }
    }
}

// ---------------------------------------------------------------------------
// Double-buffered fp32 GEMM (small GEMMs: kv / q / mhc)
// ---------------------------------------------------------------------------
__global__ void __launch_bounds__(256, 4)
gemm2_kernel(const float* __restrict__ A, const float* __restrict__ W,
             const float* __restrict__ bias, float* __restrict__ C,
             int Nd, int Kd, int lda, int ldc, int relu)
{
    constexpr int BM = 64, BN = 64, BK = 16;
    __shared__ float As[2][BK][BM + 4];
    __shared__ float Bs[2][BK][BN + 4];

    const int tid = threadIdx.x;
    const int tx = tid & 15;
    const int ty = tid >> 4;
    const int row0 = blockIdx.y * BM;
    const int col0 = blockIdx.x * BN;

    const int am = tid >> 2;
    const int ak = (tid & 3) * 4;
    const int bk = tid >> 4;
    const int bn = (tid & 15) * 4;

    const int TILES = Kd / BK;

    float4 ra, rb;
    ra = *(const float4*)&A[(size_t)(row0 + am) * lda + ak];
    rb = *(const float4*)&W[(size_t)bk * Nd + col0 + bn];
    As[0][ak + 0][am] = ra.x; As[0][ak + 1][am] = ra.y;
    As[0][ak + 2][am] = ra.z; As[0][ak + 3][am] = ra.w;
    *(float4*)&Bs[0][bk][bn] = rb;
    __syncthreads();

    float acc[4][4];
#pragma unroll
    for (int i = 0; i < 4; i++)
#pragma unroll
        for (int j = 0; j < 4; j++) acc[i][j] = 0.f;

    for (int t = 0; t < TILES; t++) {
        int buf = t & 1;
        if (t + 1 < TILES) {
            ra = *(const float4*)&A[(size_t)(row0 + am) * lda + (t + 1) * BK + ak];
            rb = *(const float4*)&W[(size_t)((t + 1) * BK + bk) * Nd + col0 + bn];
        }
#pragma unroll
        for (int kk = 0; kk < BK; kk++) {
            float4 av = *(const float4*)&As[buf][kk][ty * 4];
            float4 bv = *(const float4*)&Bs[buf][kk][tx * 4];
            float a[4] = {av.x, av.y, av.z, av.w};
            float b[4] = {bv.x, bv.y, bv.z, bv.w};
#pragma unroll
            for (int i = 0; i < 4; i++)
#pragma unroll
                for (int j = 0; j < 4; j++) acc[i][j] += a[i] * b[j];
        }
        if (t + 1 < TILES) {
            int nb = buf ^ 1;
            As[nb][ak + 0][am] = ra.x; As[nb][ak + 1][am] = ra.y;
            As[nb][ak + 2][am] = ra.z; As[nb][ak + 3][am] = ra.w;
            *(float4*)&Bs[nb][bk][bn] = rb;
        }
        __syncthreads();
    }

    float bs[4] = {0.f, 0.f, 0.f, 0.f};
    if (bias) {
#pragma unroll
        for (int j = 0; j < 4; j++) bs[j] = bias[col0 + tx * 4 + j];
    }
#pragma unroll
    for (int i = 0; i < 4; i++) {
        int gm = row0 + ty * 4 + i;
        float4 r;
        float rr[4];
#pragma unroll
        for (int j = 0; j < 4; j++) {
            float x = acc[i][j] + bs[j];
            rr[j] = relu ? fmaxf(x, 0.f) : x;
        }
        r.x = rr[0]; r.y = rr[1]; r.z = rr[2]; r.w = rr[3];
        *(float4*)&C[(size_t)gm * ldc + col0 + tx * 4] = r;
    }
}

// ---------------------------------------------------------------------------
// Attention: block per (b, h, 8-row tile). 128 threads.
// ---------------------------------------------------------------------------
__global__ void __launch_bounds__(128, 4)
attn_kernel(const float* __restrict__ ninf)
{
    __shared__ float q_s[8][QK_];
    __shared__ float k_s[QK_][N_ + 8];
    __shared__ float v_s[N_][QK_];
    __shared__ float w_s[8][N_];

    const int rtile = blockIdx.x;
    const int h = blockIdx.y;
    const int b = blockIdx.z;
    const int row0 = b * R_ + rtile * 8;
    const int tid = threadIdx.x;
    const int w = tid >> 5;
    const int lane = tid & 31;

    if (tid < 8 * QK_) {
        int rl = tid >> 4, d = tid & 15;
        q_s[rl][d] = g_q[(size_t)(row0 + rl) * D_ + h * QK_ + d];
    }
    const float* kvb = g_kv + (size_t)b * N_ * (2 * D_) + h * QK_;
    for (int idx = tid; idx < N_ * QK_; idx += 128) {
        int n = idx >> 4, d = idx & 15;
        k_s[d][n] = kvb[(size_t)n * (2 * D_) + d];
        v_s[n][d] = kvb[(size_t)n * (2 * D_) + D_ + d];
    }
    __syncthreads();

#pragma unroll
    for (int rr = 0; rr < 2; rr++) {
        int rl = w * 2 + rr;
        int row = row0 + rl;
        const float* maskp = ninf + (size_t)row * N_;

        float mx = -CUDART_INF_F;
        for (int n0 = 0; n0 < N_; n0 += 32) {
            int n = n0 + lane;
            float s = -CUDART_INF_F;
            if (n < N_) {
                float a = 0.f;
#pragma unroll
                for (int d = 0; d < QK_; d++) a += q_s[rl][d] * k_s[d][n];
                s = a * 0.25f + maskp[n];
                w_s[rl][n] = s;
            }
            mx = fmaxf(mx, s);
        }
#pragma unroll
        for (int off = 16; off > 0; off >>= 1)
            mx = fmaxf(mx, __shfl_xor_sync(0xffffffffu, mx, off));

        float sum = 0.f;
        for (int n0 = 0; n0 < N_; n0 += 32) {
            int n = n0 + lane;
            if (n < N_) {
                float e = __expf(w_s[rl][n] - mx);
                w_s[rl][n] = e;
                sum += e;
            }
        }
#pragma unroll
        for (int off = 16; off > 0; off >>= 1)
            sum += __shfl_xor_sync(0xffffffffu, sum, off);
        float inv = 1.f / sum;
        __syncwarp();

        int d = lane & 15;
        int half = lane >> 4;
        float acc = 0.f;
#pragma unroll 2
        for (int n = half; n < N_; n += 2)
            acc += w_s[rl][n] * v_s[n][d];
        acc += __shfl_xor_sync(0xffffffffu, acc, 16);
        if (lane < QK_)
            g_att[(size_t)row * D_ + h * QK_ + d] = acc * inv;
        __syncwarp();
    }
}

// ---------------------------------------------------------------------------
// Final: block per 8-row tile.
// ---------------------------------------------------------------------------
__global__ void __launch_bounds__(256, 4)
final_kernel(const float* __restrict__ enc,
             const float* __restrict__ ninf,
             float* __restrict__ out)
{
    __shared__ float mh_s[8][D_];
    __shared__ float enc_s[32][D_ + 4];
    __shared__ float lg_s[8][N_];

    const int row0 = blockIdx.x * 8;
    const int b = row0 / R_;
    const int tid = threadIdx.x;

    {
        int r = tid >> 5, dw = tid & 31;
        *(float4*)&mh_s[r][dw * 4] =
            *(const float4*)&g_mh[(size_t)(row0 + r) * D_ + dw * 4];
    }
    __syncthreads();

    const int r = tid >> 5;
    const int nl = tid & 31;
    const float* encb = enc + (size_t)b * N_ * D_;

    for (int n0 = 0; n0 < N_; n0 += 32) {
        int nrem = N_ - n0; if (nrem > 32) nrem = 32;
        for (int v = tid; v < 32 * 32; v += 256) {
            int n = v >> 5, dw = v & 31;
            if (n < nrem)
                *(float4*)&enc_s[n][dw * 4] =
                    *(const float4*)&encb[(size_t)(n0 + n) * D_ + dw * 4];
        }
        __syncthreads();
        if (nl < nrem) {
            float acc = 0.f;
#pragma unroll
            for (int d = 0; d < D_; d += 4) {
                float4 m4 = *(const float4*)&mh_s[r][d];
                float4 e4 = *(const float4*)&enc_s[nl][d];
                acc += m4.x * e4.x + m4.y * e4.y + m4.z * e4.z + m4.w * e4.w;
            }
            float sh = acc * 0.08838834764831845f;
            lg_s[r][n0 + nl] = CLIP_ * tanhf(sh)
                             + ninf[(size_t)(row0 + r) * N_ + n0 + nl];
        }
        __syncthreads();
    }

    const int w = tid >> 5;
    const int lane = tid & 31;
    float mx = -CUDART_INF_F;
    for (int n = lane; n < N_; n += 32) mx = fmaxf(mx, lg_s[w][n]);
#pragma unroll
    for (int off = 16; off > 0; off >>= 1)
        mx = fmaxf(mx, __shfl_xor_sync(0xffffffffu, mx, off));
    float sum = 0.f;
    for (int n = lane; n < N_; n += 32) {
        float e = __expf(lg_s[w][n] - mx);
        lg_s[w][n] = e;
        sum += e;
    }
#pragma unroll
    for (int off = 16; off > 0; off >>= 1)
        sum += __shfl_xor_sync(0xffffffffu, sum, off);
    float inv = 1.f / sum;
    for (int n = lane; n < N_; n += 32)
        out[(size_t)(row0 + w) * N_ + n] = lg_s[w][n] * inv;
}

// ---------------------------------------------------------------------------
// Host: launch pipeline (graph-capturable, allocation-free)
// ---------------------------------------------------------------------------
extern "C" void kernel_launch(void* const* d_in, const int* in_sizes, int n_in,
                              void* d_out, int out_size)
{
    const float* enc  = (const float*)d_in[0];
    const float* dist = (const float*)d_in[1];
    const float* mask = (const float*)d_in[2];
    const int*   cur  = (const int*)d_in[3];
    const float* Wq   = (const float*)d_in[4];
    const float* Wk   = (const float*)d_in[5];
    const float* Wv   = (const float*)d_in[6];
    const float* Wmhc = (const float*)d_in[7];
    const float* bmhc = (const float*)d_in[8];
    const float* W1   = (const float*)d_in[9];
    const float* b1   = (const float*)d_in[10];
    const float* W2   = (const float*)d_in[11];
    const float* b2   = (const float*)d_in[12];
    float* out = (float*)d_out;

    float *p_qin, *p_q, *p_kv, *p_att, *p_mh, *p_Wkv;
    __nv_bfloat16 *p_bfh, *p_bfl, *p_h1h, *p_h1l, *p_w1h, *p_w1l, *p_w2h, *p_w2l;
    cudaGetSymbolAddress((void**)&p_qin,  g_qin);
    cudaGetSymbolAddress((void**)&p_q,    g_q);
    cudaGetSymbolAddress((void**)&p_kv,   g_kv);
    cudaGetSymbolAddress((void**)&p_att,  g_att);
    cudaGetSymbolAddress((void**)&p_mh,   g_mh);
    cudaGetSymbolAddress((void**)&p_Wkv,  g_Wkv);
    cudaGetSymbolAddress((void**)&p_bfh,  g_bflat_h);
    cudaGetSymbolAddress((void**)&p_bfl,  g_bflat_l);
    cudaGetSymbolAddress((void**)&p_h1h,  g_h1_h);
    cudaGetSymbolAddress((void**)&p_h1l,  g_h1_l);
    cudaGetSymbolAddress((void**)&p_w1h,  g_w1t_h);
    cudaGetSymbolAddress((void**)&p_w1l,  g_w1t_l);
    cudaGetSymbolAddress((void**)&p_w2h,  g_w2t_h);
    cudaGetSymbolAddress((void**)&p_w2l,  g_w2t_l);

    knn_kernel<<<ROWS_ / 8, 256>>>(dist, mask, cur);
    gather_kernel<<<ROWS_, 128>>>(enc, cur);
    pack_kv_kernel<<<(D_ * 2 * D_ + 255) / 256, 256>>>(Wk, Wv);
    pack_wT_kernel<<<dim3(KNN_ * D_ / 32, 5 * D_ / 32), dim3(32, 8)>>>(
        W1, p_w1h, p_w1l, KNN_ * D_, 5 * D_);
    pack_wT_kernel<<<dim3(5 * D_ / 32, D_ / 32), dim3(32, 8)>>>(
        W2, p_w2h, p_w2l, 5 * D_, D_);

    // kv = enc @ [Wk|Wv] : M=6400, N=256, K=128
    gemm2_kernel<<<dim3(4, 100), 256>>>(enc, p_Wkv, nullptr, p_kv,
                                        2 * D_, D_, D_, 2 * D_, 0);
    // h1 = relu(bflat @ W1 + b1) : tensor-core split-bf16 (ldmatrix)
    mma_gemm_kernel<1, 1><<<dim3(5, 50), 256>>>(
        p_bfh, p_bfl, p_w1h, p_w1l, b1,
        nullptr, p_h1h, p_h1l, KNN_ * D_, 5 * D_);
    // unv = h1 @ W2 + b2 -> qin[:,128:256] : tensor-core, fp32 out (ldc=256)
    mma_gemm_kernel<0, 0><<<dim3(1, 50), 256>>>(
        p_h1h, p_h1l, p_w2h, p_w2l, b2,
        p_qin + D_, nullptr, nullptr, 5 * D_, 2 * D_);
    // q = qin @ Wq : M=6400, N=128, K=256
    gemm2_kernel<<<dim3(2, 100), 256>>>(p_qin, Wq, nullptr, p_q,
                                        D_, 2 * D_, 2 * D_, D_, 0);

    attn_kernel<<<dim3(25, H_, B_), 128>>>(mask);

    // mh = att @ Wmhc + bmhc : M=6400, N=128, K=128
    gemm2_kernel<<<dim3(2, 100), 256>>>(p_att, Wmhc, bmhc, p_mh,
                                        D_, D_, D_, D_, 0);

    final_kernel<<<ROWS_ / 8, 256>>>(enc, mask, out);
}

// round 9
// speedup vs baseline: 5.5295x; 1.0099x over previous
#include <cuda_runtime.h>
#include <cuda_bf16.h>
#include <math_constants.h>
#include <math.h>

// Problem constants
#define B_    32
#define R_    200
#define N_    200
#define D_    128
#define H_    8
#define QK_   16
#define KNN_  10
#define CLIP_ 10.0f
#define ROWS_    (B_ * R_)   // 6400 decoder rows

// ---------------------------------------------------------------------------
// Scratch (device globals — no allocation allowed)
// ---------------------------------------------------------------------------
__device__ __nv_bfloat16 g_bflat_h[(size_t)ROWS_ * KNN_ * D_];  // [6400,1280]
__device__ __nv_bfloat16 g_bflat_l[(size_t)ROWS_ * KNN_ * D_];
__device__ __nv_bfloat16 g_h1_h[(size_t)ROWS_ * 5 * D_];        // [6400,640]
__device__ __nv_bfloat16 g_h1_l[(size_t)ROWS_ * 5 * D_];
__device__ __nv_bfloat16 g_w1t_h[(size_t)5 * D_ * KNN_ * D_];   // [640,1280] (transposed)
__device__ __nv_bfloat16 g_w1t_l[(size_t)5 * D_ * KNN_ * D_];
__device__ __nv_bfloat16 g_w2t_h[(size_t)D_ * 5 * D_];          // [128,640]
__device__ __nv_bfloat16 g_w2t_l[(size_t)D_ * 5 * D_];
__device__ float g_qin[(size_t)ROWS_ * 2 * D_];       // [6400,256] = [cur | unv]
__device__ float g_q[(size_t)ROWS_ * D_];
__device__ float g_kv[(size_t)ROWS_ * 2 * D_];        // [b*N+n][0:128 k | 128:256 v]
__device__ float g_att[(size_t)ROWS_ * D_];
__device__ float g_mh[(size_t)ROWS_ * D_];
__device__ float g_Wkv[(size_t)D_ * 2 * D_];          // [128][256] = [Wk | Wv]
__device__ int   g_knn[(size_t)ROWS_ * KNN_];

// ---------------------------------------------------------------------------
// 1) kNN: warp per row.
// ---------------------------------------------------------------------------
__global__ void __launch_bounds__(256)
knn_kernel(const float* __restrict__ distance,
           const float* __restrict__ ninf,
           const int* __restrict__ current)
{
    const int w = threadIdx.x >> 5;
    const int lane = threadIdx.x & 31;
    const int row = blockIdx.x * 8 + w;
    if (row >= ROWS_) return;
    const int b = row / R_;
    const int cur = current[row];
    const float* dist = distance + ((size_t)b * N_ + cur) * N_;
    const float* mp = ninf + (size_t)row * N_;

    float v[7];
#pragma unroll
    for (int i = 0; i < 7; i++) {
        int n = lane + 32 * i;
        if (n < N_) {
            float m = mp[n];
            v[i] = isinf(m) ? CUDART_INF_F : dist[n];
        } else {
            v[i] = CUDART_INF_F;
        }
    }

#pragma unroll
    for (int j = 0; j < KNN_; j++) {
        float bv = v[0]; int bi = lane;
#pragma unroll
        for (int i = 1; i < 7; i++) {
            if (v[i] < bv) { bv = v[i]; bi = lane + 32 * i; }
        }
#pragma unroll
        for (int off = 16; off > 0; off >>= 1) {
            float ov = __shfl_xor_sync(0xffffffffu, bv, off);
            int   oi = __shfl_xor_sync(0xffffffffu, bi, off);
            if (ov < bv || (ov == bv && oi < bi)) { bv = ov; bi = oi; }
        }
        int sel = isinf(bv) ? N_ : bi;
        if (lane == j) g_knn[(size_t)row * KNN_ + j] = sel;
        if (!isinf(bv) && (bi & 31) == lane) v[bi >> 5] = CUDART_INF_F;
    }
}

// ---------------------------------------------------------------------------
// 2) gather + pad-avg -> bflat (bf16 hi/lo) ; current embedding -> qin[:,0:128]
// ---------------------------------------------------------------------------
__global__ void gather_kernel(const float* __restrict__ enc,
                              const int* __restrict__ current)
{
    int row = blockIdx.x;
    int b = row / R_;
    int d = threadIdx.x;  // 128
    __shared__ int sid[KNN_];
    __shared__ int scnt;
    if (d < KNN_) sid[d] = g_knn[(size_t)row * KNN_ + d];
    __syncthreads();
    if (d == 0) {
        int c = 0;
#pragma unroll
        for (int j = 0; j < KNN_; j++) c += (sid[j] < N_);
        scnt = c;
    }
    __syncthreads();

    float v[KNN_];
    float sum = 0.f;
#pragma unroll
    for (int j = 0; j < KNN_; j++) {
        int id = sid[j];
        float x = (id < N_) ? enc[((size_t)b * N_ + id) * D_ + d] : 0.f;
        v[j] = x; sum += x;
    }
    float mean = sum / fmaxf((float)scnt, 1e-9f);
#pragma unroll
    for (int j = 0; j < KNN_; j++) {
        float x = (sid[j] < N_) ? v[j] : mean;
        __nv_bfloat16 hi = __float2bfloat16_rn(x);
        __nv_bfloat16 lo = __float2bfloat16_rn(x - __bfloat162float(hi));
        size_t o = (size_t)row * (KNN_ * D_) + j * D_ + d;
        g_bflat_h[o] = hi;
        g_bflat_l[o] = lo;
    }

    int cur = current[row];
    g_qin[(size_t)row * (2 * D_) + d] = enc[((size_t)b * N_ + cur) * D_ + d];
}

// ---------------------------------------------------------------------------
// pack [Wk | Wv] -> g_Wkv [128][256]
// ---------------------------------------------------------------------------
__global__ void pack_kv_kernel(const float* __restrict__ Wk,
                               const float* __restrict__ Wv)
{
    int i = blockIdx.x * blockDim.x + threadIdx.x;
    if (i >= D_ * 2 * D_) return;
    int k = i / (2 * D_);
    int n = i % (2 * D_);
    g_Wkv[i] = (n < D_) ? Wk[(size_t)k * D_ + n] : Wv[(size_t)k * D_ + (n - D_)];
}

// ---------------------------------------------------------------------------
// Tiled transpose + bf16 split: W[K][N] -> T_hi/T_lo [N][K]. 32x32 tiles,
// block (32,8). K, N multiples of 32. Coalesced both sides.
// ---------------------------------------------------------------------------
__global__ void pack_wT_kernel(const float* __restrict__ W,
                               __nv_bfloat16* __restrict__ Th,
                               __nv_bfloat16* __restrict__ Tl,
                               int K, int Nd)
{
    __shared__ float tile[32][33];
    const int k0 = blockIdx.x * 32;
    const int n0 = blockIdx.y * 32;
    const int tx = threadIdx.x;
    const int ty = threadIdx.y;
#pragma unroll
    for (int j = 0; j < 4; j++)
        tile[ty + 8 * j][tx] = W[(size_t)(k0 + ty + 8 * j) * Nd + n0 + tx];
    __syncthreads();
#pragma unroll
    for (int j = 0; j < 4; j++) {
        float x = tile[tx][ty + 8 * j];
        __nv_bfloat16 hi = __float2bfloat16_rn(x);
        size_t o = (size_t)(n0 + ty + 8 * j) * K + k0 + tx;
        Th[o] = hi;
        Tl[o] = __float2bfloat16_rn(x - __bfloat162float(hi));
    }
}

// ---------------------------------------------------------------------------
// ldmatrix helper
// ---------------------------------------------------------------------------
#define LDMX4(r0, r1, r2, r3, addr)                                         \
    asm volatile("ldmatrix.sync.aligned.m8n8.x4.shared.b16 "                \
                 "{%0,%1,%2,%3}, [%4];"                                     \
                 : "=r"(r0), "=r"(r1), "=r"(r2), "=r"(r3) : "r"(addr))

#define MMA_BF16(cc, a0, a1, a2, a3, b0, b1)                                \
    asm volatile("mma.sync.aligned.m16n8k16.row.col.f32.bf16.bf16.f32 "     \
                 "{%0,%1,%2,%3},{%4,%5,%6,%7},{%8,%9},{%0,%1,%2,%3};"       \
                 : "+f"(cc[0]), "+f"(cc[1]), "+f"(cc[2]), "+f"(cc[3])       \
                 : "r"(a0), "r"(a1), "r"(a2), "r"(a3), "r"(b0), "r"(b1))

// ---------------------------------------------------------------------------
// Split-bf16 tensor GEMM with ldmatrix: C = A @ B^T (+bias).
// A=[M,K] hi/lo bf16 k-major; B=[N,K] hi/lo bf16 k-major.
// Block 128x128, BK=16, 8 warps (64x32). 3 HMMA passes (hh, hl, lh).
// smem row layout (80 B stride, conflict-free ldmatrix):
//   words 0-7: hi k0-15, words 8-15: lo k0-15, words 16-19: pad
// ---------------------------------------------------------------------------
template <int RELU, int SPLIT_OUT>
__global__ void __launch_bounds__(256, 2)
mma_gemm_kernel(const __nv_bfloat16* __restrict__ Ah,
                const __nv_bfloat16* __restrict__ Al,
                const __nv_bfloat16* __restrict__ Bh,
                const __nv_bfloat16* __restrict__ Bl,
                const float* __restrict__ bias,
                float* __restrict__ Cf,
                __nv_bfloat16* __restrict__ Ch,
                __nv_bfloat16* __restrict__ Cl,
                int Kd, int ldc)
{
    __shared__ unsigned As[2][128][20];
    __shared__ unsigned Bs[2][128][20];

    const int tid = threadIdx.x;
    const int lane = tid & 31;
    const int wid = tid >> 5;
    const int wm = (wid & 1) * 64;
    const int wn = (wid >> 1) * 32;
    const int row0 = blockIdx.y * 128;
    const int col0 = blockIdx.x * 128;

    // loader mapping: thread -> (row, k-half), one uint4 (8 bf16) per array
    const int l_r = tid >> 1;
    const int l_h = tid & 1;
    const size_t a_base = (size_t)(row0 + l_r) * Kd + l_h * 8;
    const size_t b_base = (size_t)(col0 + l_r) * Kd + l_h * 8;

    const unsigned as0 = (unsigned)__cvta_generic_to_shared(&As[0][0][0]);
    const unsigned bs0 = (unsigned)__cvta_generic_to_shared(&Bs[0][0][0]);
    const unsigned BUFB = 128 * 20 * 4;   // bytes per buffer

    // ldmatrix per-lane offsets (bytes), hi; lo = +32
    const unsigned a_lm = (unsigned)((lane & 15) * 80 + (lane >> 4) * 16);
    const unsigned b_lm = (unsigned)(((lane & 7) + ((lane >> 4) << 3)) * 80 +
                                     ((lane >> 3) & 1) * 16);

    const int TILES = Kd / 16;

    uint4 pah, pal, pbh, pbl;
    pah = *(const uint4*)&Ah[a_base];
    pal = *(const uint4*)&Al[a_base];
    pbh = *(const uint4*)&Bh[b_base];
    pbl = *(const uint4*)&Bl[b_base];
    {
        *(uint4*)&As[0][l_r][l_h * 4] = pah;
        *(uint4*)&As[0][l_r][8 + l_h * 4] = pal;
        *(uint4*)&Bs[0][l_r][l_h * 4] = pbh;
        *(uint4*)&Bs[0][l_r][8 + l_h * 4] = pbl;
    }
    __syncthreads();

    float c[4][4][4];
#pragma unroll
    for (int i = 0; i < 4; i++)
#pragma unroll
        for (int j = 0; j < 4; j++)
#pragma unroll
            for (int r = 0; r < 4; r++) c[i][j][r] = 0.f;

    for (int t = 0; t < TILES; t++) {
        const int buf = t & 1;
        const unsigned bof = buf * BUFB;
        if (t + 1 < TILES) {
            const size_t ko = (size_t)(t + 1) * 16;
            pah = *(const uint4*)&Ah[a_base + ko];
            pal = *(const uint4*)&Al[a_base + ko];
            pbh = *(const uint4*)&Bh[b_base + ko];
            pbl = *(const uint4*)&Bl[b_base + ko];
        }

        // B fragments: 4 n-tiles x {b0,b1} x {hi,lo} via 4 ldmatrix.x4
        unsigned bh[4][2], bl[4][2];
#pragma unroll
        for (int np = 0; np < 2; np++) {
            unsigned addr = bs0 + bof + (wn + np * 16) * 80 + b_lm;
            LDMX4(bh[2 * np][0], bh[2 * np][1],
                  bh[2 * np + 1][0], bh[2 * np + 1][1], addr);
            LDMX4(bl[2 * np][0], bl[2 * np][1],
                  bl[2 * np + 1][0], bl[2 * np + 1][1], addr + 32);
        }

#pragma unroll
        for (int mt = 0; mt < 4; mt++) {
            unsigned aaddr = as0 + bof + (wm + mt * 16) * 80 + a_lm;
            unsigned ah0, ah1, ah2, ah3, al0, al1, al2, al3;
            LDMX4(ah0, ah1, ah2, ah3, aaddr);
            LDMX4(al0, al1, al2, al3, aaddr + 32);
#pragma unroll
            for (int nt = 0; nt < 4; nt++) {
                float* cc = c[mt][nt];
                MMA_BF16(cc, ah0, ah1, ah2, ah3, bh[nt][0], bh[nt][1]);
                MMA_BF16(cc, ah0, ah1, ah2, ah3, bl[nt][0], bl[nt][1]);
                MMA_BF16(cc, al0, al1, al2, al3, bh[nt][0], bh[nt][1]);
            }
        }

        if (t + 1 < TILES) {
            const int nb = buf ^ 1;
            *(uint4*)&As[nb][l_r][l_h * 4] = pah;
            *(uint4*)&As[nb][l_r][8 + l_h * 4] = pal;
            *(uint4*)&Bs[nb][l_r][l_h * 4] = pbh;
            *(uint4*)&Bs[nb][l_r][8 + l_h * 4] = pbl;
        }
        __syncthreads();
    }

    // epilogue
    const int g = lane >> 2;
    const int kp = lane & 3;
#pragma unroll
    for (int mt = 0; mt < 4; mt++) {
#pragma unroll
        for (int nt = 0; nt < 4; nt++) {
            const int row = row0 + wm + mt * 16 + g;
            const int col = col0 + wn + nt * 8 + 2 * kp;
            float b0 = bias ? bias[col] : 0.f;
            float b1 = bias ? bias[col + 1] : 0.f;
            float v00 = c[mt][nt][0] + b0, v01 = c[mt][nt][1] + b1;
            float v10 = c[mt][nt][2] + b0, v11 = c[mt][nt][3] + b1;
            if (RELU) {
                v00 = fmaxf(v00, 0.f); v01 = fmaxf(v01, 0.f);
                v10 = fmaxf(v10, 0.f); v11 = fmaxf(v11, 0.f);
            }
            if (SPLIT_OUT) {
                __nv_bfloat16 h00 = __float2bfloat16_rn(v00);
                __nv_bfloat16 h01 = __float2bfloat16_rn(v01);
                __nv_bfloat16 h10 = __float2bfloat16_rn(v10);
                __nv_bfloat16 h11 = __float2bfloat16_rn(v11);
                __nv_bfloat162 hp0 = {h00, h01};
                __nv_bfloat162 hp1 = {h10, h11};
                __nv_bfloat162 lp0 = {__float2bfloat16_rn(v00 - __bfloat162float(h00)),
                                      __float2bfloat16_rn(v01 - __bfloat162float(h01))};
                __nv_bfloat162 lp1 = {__float2bfloat16_rn(v10 - __bfloat162float(h10)),
                                      __float2bfloat16_rn(v11 - __bfloat162float(h11))};
                *(__nv_bfloat162*)&Ch[(size_t)row * ldc + col] = hp0;
                *(__nv_bfloat162*)&Ch[(size_t)(row + 8) * ldc + col] = hp1;
                *(__nv_bfloat162*)&Cl[(size_t)row * ldc + col] = lp0;
                *(__nv_bfloat162*)&Cl[(size_t)(row + 8) * ldc + col] = lp1;
            } else {
                float2 f0 = {v00, v01};
                float2 f1 = {v10, v11};
                *(float2*)&Cf[(size_t)row * ldc + col] = f0;
                *(float2*)&Cf[(size_t)(row + 8) * ldc + col] = f1;
            }
        }
    }
}

// ---------------------------------------------------------------------------
// Double-buffered fp32 GEMM (small GEMMs: kv / q / mhc)
// ---------------------------------------------------------------------------
__global__ void __launch_bounds__(256, 4)
gemm2_kernel(const float* __restrict__ A, const float* __restrict__ W,
             const float* __restrict__ bias, float* __restrict__ C,
             int Nd, int Kd, int lda, int ldc, int relu)
{
    constexpr int BM = 64, BN = 64, BK = 16;
    __shared__ float As[2][BK][BM + 4];
    __shared__ float Bs[2][BK][BN + 4];

    const int tid = threadIdx.x;
    const int tx = tid & 15;
    const int ty = tid >> 4;
    const int row0 = blockIdx.y * BM;
    const int col0 = blockIdx.x * BN;

    const int am = tid >> 2;
    const int ak = (tid & 3) * 4;
    const int bk = tid >> 4;
    const int bn = (tid & 15) * 4;

    const int TILES = Kd / BK;

    float4 ra, rb;
    ra = *(const float4*)&A[(size_t)(row0 + am) * lda + ak];
    rb = *(const float4*)&W[(size_t)bk * Nd + col0 + bn];
    As[0][ak + 0][am] = ra.x; As[0][ak + 1][am] = ra.y;
    As[0][ak + 2][am] = ra.z; As[0][ak + 3][am] = ra.w;
    *(float4*)&Bs[0][bk][bn] = rb;
    __syncthreads();

    float acc[4][4];
#pragma unroll
    for (int i = 0; i < 4; i++)
#pragma unroll
        for (int j = 0; j < 4; j++) acc[i][j] = 0.f;

    for (int t = 0; t < TILES; t++) {
        int buf = t & 1;
        if (t + 1 < TILES) {
            ra = *(const float4*)&A[(size_t)(row0 + am) * lda + (t + 1) * BK + ak];
            rb = *(const float4*)&W[(size_t)((t + 1) * BK + bk) * Nd + col0 + bn];
        }
#pragma unroll
        for (int kk = 0; kk < BK; kk++) {
            float4 av = *(const float4*)&As[buf][kk][ty * 4];
            float4 bv = *(const float4*)&Bs[buf][kk][tx * 4];
            float a[4] = {av.x, av.y, av.z, av.w};
            float b[4] = {bv.x, bv.y, bv.z, bv.w};
#pragma unroll
            for (int i = 0; i < 4; i++)
#pragma unroll
                for (int j = 0; j < 4; j++) acc[i][j] += a[i] * b[j];
        }
        if (t + 1 < TILES) {
            int nb = buf ^ 1;
            As[nb][ak + 0][am] = ra.x; As[nb][ak + 1][am] = ra.y;
            As[nb][ak + 2][am] = ra.z; As[nb][ak + 3][am] = ra.w;
            *(float4*)&Bs[nb][bk][bn] = rb;
        }
        __syncthreads();
    }

    float bs[4] = {0.f, 0.f, 0.f, 0.f};
    if (bias) {
#pragma unroll
        for (int j = 0; j < 4; j++) bs[j] = bias[col0 + tx * 4 + j];
    }
#pragma unroll
    for (int i = 0; i < 4; i++) {
        int gm = row0 + ty * 4 + i;
        float4 r;
        float rr[4];
#pragma unroll
        for (int j = 0; j < 4; j++) {
            float x = acc[i][j] + bs[j];
            rr[j] = relu ? fmaxf(x, 0.f) : x;
        }
        r.x = rr[0]; r.y = rr[1]; r.z = rr[2]; r.w = rr[3];
        *(float4*)&C[(size_t)gm * ldc + col0 + tx * 4] = r;
    }
}

// ---------------------------------------------------------------------------
// Attention: block per (b, h, 8-row tile). 128 threads.
// ---------------------------------------------------------------------------
__global__ void __launch_bounds__(128, 4)
attn_kernel(const float* __restrict__ ninf)
{
    __shared__ float q_s[8][QK_];
    __shared__ float k_s[QK_][N_ + 8];
    __shared__ float v_s[N_][QK_];
    __shared__ float w_s[8][N_];

    const int rtile = blockIdx.x;
    const int h = blockIdx.y;
    const int b = blockIdx.z;
    const int row0 = b * R_ + rtile * 8;
    const int tid = threadIdx.x;
    const int w = tid >> 5;
    const int lane = tid & 31;

    if (tid < 8 * QK_) {
        int rl = tid >> 4, d = tid & 15;
        q_s[rl][d] = g_q[(size_t)(row0 + rl) * D_ + h * QK_ + d];
    }
    const float* kvb = g_kv + (size_t)b * N_ * (2 * D_) + h * QK_;
    for (int idx = tid; idx < N_ * QK_; idx += 128) {
        int n = idx >> 4, d = idx & 15;
        k_s[d][n] = kvb[(size_t)n * (2 * D_) + d];
        v_s[n][d] = kvb[(size_t)n * (2 * D_) + D_ + d];
    }
    __syncthreads();

#pragma unroll
    for (int rr = 0; rr < 2; rr++) {
        int rl = w * 2 + rr;
        int row = row0 + rl;
        const float* maskp = ninf + (size_t)row * N_;

        float mx = -CUDART_INF_F;
        for (int n0 = 0; n0 < N_; n0 += 32) {
            int n = n0 + lane;
            float s = -CUDART_INF_F;
            if (n < N_) {
                float a = 0.f;
#pragma unroll
                for (int d = 0; d < QK_; d++) a += q_s[rl][d] * k_s[d][n];
                s = a * 0.25f + maskp[n];
                w_s[rl][n] = s;
            }
            mx = fmaxf(mx, s);
        }
#pragma unroll
        for (int off = 16; off > 0; off >>= 1)
            mx = fmaxf(mx, __shfl_xor_sync(0xffffffffu, mx, off));

        float sum = 0.f;
        for (int n0 = 0; n0 < N_; n0 += 32) {
            int n = n0 + lane;
            if (n < N_) {
                float e = __expf(w_s[rl][n] - mx);
                w_s[rl][n] = e;
                sum += e;
            }
        }
#pragma unroll
        for (int off = 16; off > 0; off >>= 1)
            sum += __shfl_xor_sync(0xffffffffu, sum, off);
        float inv = 1.f / sum;
        __syncwarp();

        int d = lane & 15;
        int half = lane >> 4;
        float acc = 0.f;
#pragma unroll 2
        for (int n = half; n < N_; n += 2)
            acc += w_s[rl][n] * v_s[n][d];
        acc += __shfl_xor_sync(0xffffffffu, acc, 16);
        if (lane < QK_)
            g_att[(size_t)row * D_ + h * QK_ + d] = acc * inv;
        __syncwarp();
    }
}

// ---------------------------------------------------------------------------
// Final: block per 8-row tile.
// ---------------------------------------------------------------------------
__global__ void __launch_bounds__(256, 4)
final_kernel(const float* __restrict__ enc,
             const float* __restrict__ ninf,
             float* __restrict__ out)
{
    __shared__ float mh_s[8][D_];
    __shared__ float enc_s[32][D_ + 4];
    __shared__ float lg_s[8][N_];

    const int row0 = blockIdx.x * 8;
    const int b = row0 / R_;
    const int tid = threadIdx.x;

    {
        int r = tid >> 5, dw = tid & 31;
        *(float4*)&mh_s[r][dw * 4] =
            *(const float4*)&g_mh[(size_t)(row0 + r) * D_ + dw * 4];
    }
    __syncthreads();

    const int r = tid >> 5;
    const int nl = tid & 31;
    const float* encb = enc + (size_t)b * N_ * D_;

    for (int n0 = 0; n0 < N_; n0 += 32) {
        int nrem = N_ - n0; if (nrem > 32) nrem = 32;
        for (int v = tid; v < 32 * 32; v += 256) {
            int n = v >> 5, dw = v & 31;
            if (n < nrem)
                *(float4*)&enc_s[n][dw * 4] =
                    *(const float4*)&encb[(size_t)(n0 + n) * D_ + dw * 4];
        }
        __syncthreads();
        if (nl < nrem) {
            float acc = 0.f;
#pragma unroll
            for (int d = 0; d < D_; d += 4) {
                float4 m4 = *(const float4*)&mh_s[r][d];
                float4 e4 = *(const float4*)&enc_s[nl][d];
                acc += m4.x * e4.x + m4.y * e4.y + m4.z * e4.z + m4.w * e4.w;
            }
            float sh = acc * 0.08838834764831845f;
            lg_s[r][n0 + nl] = CLIP_ * tanhf(sh)
                             + ninf[(size_t)(row0 + r) * N_ + n0 + nl];
        }
        __syncthreads();
    }

    const int w = tid >> 5;
    const int lane = tid & 31;
    float mx = -CUDART_INF_F;
    for (int n = lane; n < N_; n += 32) mx = fmaxf(mx, lg_s[w][n]);
#pragma unroll
    for (int off = 16; off > 0; off >>= 1)
        mx = fmaxf(mx, __shfl_xor_sync(0xffffffffu, mx, off));
    float sum = 0.f;
    for (int n = lane; n < N_; n += 32) {
        float e = __expf(lg_s[w][n] - mx);
        lg_s[w][n] = e;
        sum += e;
    }
#pragma unroll
    for (int off = 16; off > 0; off >>= 1)
        sum += __shfl_xor_sync(0xffffffffu, sum, off);
    float inv = 1.f / sum;
    for (int n = lane; n < N_; n += 32)
        out[(size_t)(row0 + w) * N_ + n] = lg_s[w][n] * inv;
}

// ---------------------------------------------------------------------------
// Host: launch pipeline (graph-capturable, allocation-free)
// ---------------------------------------------------------------------------
extern "C" void kernel_launch(void* const* d_in, const int* in_sizes, int n_in,
                              void* d_out, int out_size)
{
    const float* enc  = (const float*)d_in[0];
    const float* dist = (const float*)d_in[1];
    const float* mask = (const float*)d_in[2];
    const int*   cur  = (const int*)d_in[3];
    const float* Wq   = (const float*)d_in[4];
    const float* Wk   = (const float*)d_in[5];
    const float* Wv   = (const float*)d_in[6];
    const float* Wmhc = (const float*)d_in[7];
    const float* bmhc = (const float*)d_in[8];
    const float* W1   = (const float*)d_in[9];
    const float* b1   = (const float*)d_in[10];
    const float* W2   = (const float*)d_in[11];
    const float* b2   = (const float*)d_in[12];
    float* out = (float*)d_out;

    float *p_qin, *p_q, *p_kv, *p_att, *p_mh, *p_Wkv;
    __nv_bfloat16 *p_bfh, *p_bfl, *p_h1h, *p_h1l, *p_w1h, *p_w1l, *p_w2h, *p_w2l;
    cudaGetSymbolAddress((void**)&p_qin,  g_qin);
    cudaGetSymbolAddress((void**)&p_q,    g_q);
    cudaGetSymbolAddress((void**)&p_kv,   g_kv);
    cudaGetSymbolAddress((void**)&p_att,  g_att);
    cudaGetSymbolAddress((void**)&p_mh,   g_mh);
    cudaGetSymbolAddress((void**)&p_Wkv,  g_Wkv);
    cudaGetSymbolAddress((void**)&p_bfh,  g_bflat_h);
    cudaGetSymbolAddress((void**)&p_bfl,  g_bflat_l);
    cudaGetSymbolAddress((void**)&p_h1h,  g_h1_h);
    cudaGetSymbolAddress((void**)&p_h1l,  g_h1_l);
    cudaGetSymbolAddress((void**)&p_w1h,  g_w1t_h);
    cudaGetSymbolAddress((void**)&p_w1l,  g_w1t_l);
    cudaGetSymbolAddress((void**)&p_w2h,  g_w2t_h);
    cudaGetSymbolAddress((void**)&p_w2l,  g_w2t_l);

    knn_kernel<<<ROWS_ / 8, 256>>>(dist, mask, cur);
    gather_kernel<<<ROWS_, 128>>>(enc, cur);
    pack_kv_kernel<<<(D_ * 2 * D_ + 255) / 256, 256>>>(Wk, Wv);
    pack_wT_kernel<<<dim3(KNN_ * D_ / 32, 5 * D_ / 32), dim3(32, 8)>>>(
        W1, p_w1h, p_w1l, KNN_ * D_, 5 * D_);
    pack_wT_kernel<<<dim3(5 * D_ / 32, D_ / 32), dim3(32, 8)>>>(
        W2, p_w2h, p_w2l, 5 * D_, D_);

    // kv = enc @ [Wk|Wv] : M=6400, N=256, K=128
    gemm2_kernel<<<dim3(4, 100), 256>>>(enc, p_Wkv, nullptr, p_kv,
                                        2 * D_, D_, D_, 2 * D_, 0);
    // h1 = relu(bflat @ W1 + b1) : tensor-core split-bf16 (ldmatrix)
    mma_gemm_kernel<1, 1><<<dim3(5, 50), 256>>>(
        p_bfh, p_bfl, p_w1h, p_w1l, b1,
        nullptr, p_h1h, p_h1l, KNN_ * D_, 5 * D_);
    // unv = h1 @ W2 + b2 -> qin[:,128:256] : tensor-core, fp32 out (ldc=256)
    mma_gemm_kernel<0, 0><<<dim3(1, 50), 256>>>(
        p_h1h, p_h1l, p_w2h, p_w2l, b2,
        p_qin + D_, nullptr, nullptr, 5 * D_, 2 * D_);
    // q = qin @ Wq : M=6400, N=128, K=256
    gemm2_kernel<<<dim3(2, 100), 256>>>(p_qin, Wq, nullptr, p_q,
                                        D_, 2 * D_, 2 * D_, D_, 0);

    attn_kernel<<<dim3(25, H_, B_), 128>>>(mask);

    // mh = att @ Wmhc + bmhc : M=6400, N=128, K=128
    gemm2_kernel<<<dim3(2, 100), 256>>>(p_att, Wmhc, bmhc, p_mh,
                                        D_, D_, D_, D_, 0);

    final_kernel<<<ROWS_ / 8, 256>>>(enc, mask, out);
}